// round 7
// baseline (speedup 1.0000x reference)
#include <cuda_runtime.h>
#include <cstdint>
#include <math.h>

#define TT 4096
#define DD 896

constexpr int NBLK = 32;        // 128-row blocks
constexpr int NPAIR = 528;      // causal 128x128 block pairs
constexpr int NKT = 28;         // DD/32 k-chunks
constexpr int SLA = 4096;       // words per [blk][kt] A/B slab (128x32 floats)
constexpr int SLAI = 8192;      // interleaved hi/lo A slab

// ---------------- scratch (device globals: allocation-free) ----------------
__device__ float g_h[(size_t)TT * DD];
__device__ float g_g[(size_t)TT * DD];
__device__ float g_sim[(size_t)TT * TT];       // logits scratch
__device__ float g_hn2[TT];
__device__ float g_maxQ[TT];
__device__ float g_invden[TT];

// fragment-packed operands (tf32 bit patterns)
__device__ unsigned P_hA [(size_t)NBLK * NKT * SLA];    // h, A-layout, hi (sim A, 1x)
__device__ unsigned P_hBh[(size_t)NBLK * NKT * SLA];    // h, B n-major, hi (sim B, cross B)
__device__ unsigned P_hBl[(size_t)NBLK * NKT * SLA];    // h, B n-major, lo (cross B)
__device__ unsigned P_hKh[(size_t)7 * 128 * SLA];       // h^T, B k-major, hi (g B)
__device__ unsigned P_hKl[(size_t)7 * 128 * SLA];       // lo
__device__ unsigned P_gA [(size_t)NBLK * NKT * SLAI];   // g, A-layout, hi/lo interleaved
__device__ unsigned P_aA [(size_t)NBLK * 128 * SLAI];   // alpha, A-layout, hi/lo interleaved

// ---------------- small helpers ----------------
__device__ __forceinline__ unsigned f2tf(float f) {
    unsigned u;
    asm("cvt.rna.tf32.f32 %0, %1;" : "=r"(u) : "f"(f));
    return u;
}
__device__ __forceinline__ void tfsplit(float f, unsigned& hi, unsigned& lo) {
    hi = f2tf(f);
    lo = f2tf(f - __uint_as_float(hi));
}
__device__ __forceinline__ void mma8(float* d, const unsigned* a, const unsigned* b) {
    asm volatile(
        "mma.sync.aligned.m16n8k8.row.col.f32.tf32.tf32.f32 "
        "{%0,%1,%2,%3}, {%4,%5,%6,%7}, {%8,%9}, {%0,%1,%2,%3};\n"
        : "+f"(d[0]), "+f"(d[1]), "+f"(d[2]), "+f"(d[3])
        : "r"(a[0]), "r"(a[1]), "r"(a[2]), "r"(a[3]),
          "r"(b[0]), "r"(b[1]));
}
__device__ __forceinline__ float blockReduceSum(float v, float* sh) {
    int lane = threadIdx.x & 31, w = threadIdx.x >> 5;
#pragma unroll
    for (int o = 16; o; o >>= 1) v += __shfl_xor_sync(0xffffffffu, v, o);
    __syncthreads();
    if (lane == 0) sh[w] = v;
    __syncthreads();
    if (threadIdx.x == 0) {
        float s = 0.f;
        int nw = (blockDim.x + 31) >> 5;
        for (int i = 0; i < nw; i++) s += sh[i];
        sh[0] = s;
    }
    __syncthreads();
    return sh[0];
}
__device__ __forceinline__ float blockReduceMax(float v, float* sh) {
    int lane = threadIdx.x & 31, w = threadIdx.x >> 5;
#pragma unroll
    for (int o = 16; o; o >>= 1) v = fmaxf(v, __shfl_xor_sync(0xffffffffu, v, o));
    __syncthreads();
    if (lane == 0) sh[w] = v;
    __syncthreads();
    if (threadIdx.x == 0) {
        float m = -3.0e38f;
        int nw = (blockDim.x + 31) >> 5;
        for (int i = 0; i < nw; i++) m = fmaxf(m, sh[i]);
        sh[0] = m;
    }
    __syncthreads();
    return sh[0];
}
__device__ __forceinline__ void atomicMaxF(float* addr, float val) {
    int old = __float_as_int(*addr);
    while (__int_as_float(old) < val) {
        int assumed = old;
        old = atomicCAS((int*)addr, assumed, __float_as_int(val));
        if (old == assumed) break;
    }
}
__device__ __forceinline__ void triDecode(int b, int& ib, int& jb) {
    int i = (int)floorf((sqrtf(8.0f * (float)b + 1.0f) - 1.0f) * 0.5f);
    while ((i + 1) * (i + 2) / 2 <= b) i++;
    while (i * (i + 1) / 2 > b) i--;
    ib = i;
    jb = b - i * (i + 1) / 2;
}
// fragment word index within a 128x32 chunk (m16n8k8 row.col lane map)
__device__ __forceinline__ int wA(int m, int k) {
    int frag = (m >> 4) * 4 + (k >> 3);
    int lane = (m & 7) * 4 + (k & 3);
    int j = (((k & 7) >= 4) ? 2 : 0) + (((m & 15) >= 8) ? 1 : 0);
    return frag * 128 + lane * 4 + j;
}
__device__ __forceinline__ int wB(int n, int k) {
    int frag = (n >> 3) * 4 + (k >> 3);
    int lane = (n & 7) * 4 + (k & 3);
    int j = ((k & 7) >= 4) ? 1 : 0;
    return frag * 64 + lane * 2 + j;
}

#define ACC_INIT(acc)                      \
    _Pragma("unroll")                      \
    for (int i = 0; i < 4; i++)            \
    _Pragma("unroll")                      \
    for (int j = 0; j < 4; j++)            \
    _Pragma("unroll")                      \
    for (int e = 0; e < 4; e++) acc[i][j][e] = 0.f;

// ---------------- kernel 1: normalize + pre-pack h -------------------------
__global__ void k_normalize(const float* __restrict__ x) {
    __shared__ float sh[32];
    int t = blockIdx.x;
    const float* row = x + (size_t)t * DD;
    float ss = 0.f;
    for (int i = threadIdx.x; i < DD; i += blockDim.x) {
        float v = row[i];
        ss += v * v;
    }
    ss = blockReduceSum(ss, sh);
    float inv = 1.0f / fmaxf(sqrtf(ss), 1e-12f);
    int blk = t >> 7, m = t & 127;
    for (int d = threadIdx.x; d < DD; d += blockDim.x) {
        float v = row[d] * inv;
        g_h[(size_t)t * DD + d] = v;
        unsigned hi, lo;
        tfsplit(v, hi, lo);
        int kt = d >> 5, kk = d & 31;
        size_t sa = ((size_t)blk * NKT + kt) * SLA;
        P_hA[sa + wA(m, kk)] = hi;
        int wb = wB(m, kk);
        P_hBh[sa + wb] = hi;
        P_hBl[sa + wb] = lo;
        // transposed (k-major) layout for g-GEMM: n-role = d, k-role = t
        size_t sk = ((size_t)(d >> 7) * 128 + (t >> 5)) * SLA;
        int wk = wB(d & 127, t & 31);
        P_hKh[sk + wk] = hi;
        P_hKl[sk + wk] = lo;
    }
    if (threadIdx.x == 0) {
        g_hn2[t] = ss * inv * inv;
        g_maxQ[t] = -3.0e38f;
    }
}

__global__ void k_tables() {
    int i = blockIdx.x * 256 + threadIdx.x;
    if (i < TT)
        g_invden[i] = 1.0f / (sqrtf((float)DD) * expf(0.1f * (float)i) + 1e-8f);
}

// ---------------- kernel 2: sim = h h^T (1xTF32, fragment-direct) ----------
__global__ void __launch_bounds__(256) k_sim() {
    int tid = threadIdx.x, lane = tid & 31, warp = tid >> 5;
    int wm = warp >> 2, wn = warp & 3, gr = lane >> 2, gc = lane & 3;
    int ib, jb;
    triDecode(blockIdx.x, ib, jb);

    float acc[4][4][4];
    ACC_INIT(acc)

    const unsigned* Ab = P_hA + (size_t)ib * NKT * SLA;
    const unsigned* Bb = P_hBh + (size_t)jb * NKT * SLA;
#pragma unroll 1
    for (int kt = 0; kt < NKT; kt++) {
        const unsigned* A = Ab + kt * SLA;
        const unsigned* B = Bb + kt * SLA;
#pragma unroll
        for (int ks = 0; ks < 4; ks++) {
            unsigned a[4][4], b[4][2];
#pragma unroll
            for (int i = 0; i < 4; i++)
                *(uint4*)a[i] = *(const uint4*)&A[((wm * 4 + i) * 4 + ks) * 128 + lane * 4];
#pragma unroll
            for (int j = 0; j < 4; j++)
                *(uint2*)b[j] = *(const uint2*)&B[((wn * 4 + j) * 4 + ks) * 64 + lane * 2];
#pragma unroll
            for (int i = 0; i < 4; i++)
#pragma unroll
                for (int j = 0; j < 4; j++) mma8(acc[i][j], a[i], b[j]);
        }
    }

    int rowA = ib * 128, rowB = jb * 128;
#pragma unroll
    for (int i = 0; i < 4; i++) {
        int t = rowA + (wm * 4 + i) * 16 + gr;
#pragma unroll
        for (int j = 0; j < 4; j++) {
            int s = rowB + (wn * 4 + j) * 8 + gc * 2;
            *(float2*)&g_sim[(size_t)t * TT + s]       = make_float2(acc[i][j][0], acc[i][j][1]);
            *(float2*)&g_sim[(size_t)(t + 8) * TT + s] = make_float2(acc[i][j][2], acc[i][j][3]);
        }
    }
}

// ---------------- kernel 3: softmax -> packed alpha fragments --------------
__global__ void k_softmax() {
    __shared__ float sh[32];
    int t = blockIdx.x;
    float* row = g_sim + (size_t)t * TT;
    int n = t + 1;
    float lmax = -3.0e38f;
    for (int s = threadIdx.x; s < n; s += blockDim.x) {
        float l = row[s] * g_invden[t - s];
        row[s] = l;
        lmax = fmaxf(lmax, l);
    }
    lmax = blockReduceMax(lmax, sh);
    float lsum = 0.f;
    for (int s = threadIdx.x; s < n; s += blockDim.x) {
        float e = __expf(row[s] - lmax);
        row[s] = e;
        lsum += e;
    }
    lsum = blockReduceSum(lsum, sh);
    float inv = 1.0f / lsum;

    int blk = t >> 7, m = t & 127;
    unsigned* base = P_aA + (size_t)blk * 128 * SLAI;
    for (int s = threadIdx.x; s < n; s += blockDim.x) {
        float a = row[s] * inv;
        unsigned hi, lo;
        tfsplit(a, hi, lo);
        int widx = wA(m, s & 31) * 2;
        *(uint2*)&base[(size_t)(s >> 5) * SLAI + widx] = make_uint2(hi, lo);
    }
    int zend = ((t >> 7) + 1) * 128;    // zero alpha tail to block boundary
    for (int s = n + threadIdx.x; s < zend; s += blockDim.x) {
        int widx = wA(m, s & 31) * 2;
        *(uint2*)&base[(size_t)(s >> 5) * SLAI + widx] = make_uint2(0u, 0u);
    }
}

// ---------------- kernel 4: g = alpha @ h (3xTF32, fragment-direct) --------
__global__ void __launch_bounds__(256) k_g() {
    int tid = threadIdx.x, lane = tid & 31, warp = tid >> 5;
    int wm = warp >> 2, wn = warp & 3, gr = lane >> 2, gc = lane & 3;
    int jbD = blockIdx.x;
    int ib = 31 - blockIdx.y;          // long blocks launch first
    int nkt = (ib + 1) * 4;

    float acc[4][4][4];
    ACC_INIT(acc)

    const unsigned* Ab = P_aA + (size_t)ib * 128 * SLAI;
    const unsigned* Bhb = P_hKh + (size_t)jbD * 128 * SLA;
    const unsigned* Blb = P_hKl + (size_t)jbD * 128 * SLA;
#pragma unroll 1
    for (int kt = 0; kt < nkt; kt++) {
        const unsigned* A = Ab + (size_t)kt * SLAI;
        const unsigned* Bh = Bhb + (size_t)kt * SLA;
        const unsigned* Bl = Blb + (size_t)kt * SLA;
#pragma unroll
        for (int ks = 0; ks < 4; ks++) {
            unsigned ah[4][4], al[4][4], bh[4][2], bl[4][2];
#pragma unroll
            for (int i = 0; i < 4; i++) {
                int o = (((wm * 4 + i) * 4 + ks) * 128 + lane * 4) * 2;
                uint4 u0 = *(const uint4*)&A[o];
                uint4 u1 = *(const uint4*)&A[o + 4];
                ah[i][0] = u0.x; al[i][0] = u0.y; ah[i][1] = u0.z; al[i][1] = u0.w;
                ah[i][2] = u1.x; al[i][2] = u1.y; ah[i][3] = u1.z; al[i][3] = u1.w;
            }
#pragma unroll
            for (int j = 0; j < 4; j++) {
                int o = ((wn * 4 + j) * 4 + ks) * 64 + lane * 2;
                *(uint2*)bh[j] = *(const uint2*)&Bh[o];
                *(uint2*)bl[j] = *(const uint2*)&Bl[o];
            }
#pragma unroll
            for (int i = 0; i < 4; i++)
#pragma unroll
                for (int j = 0; j < 4; j++) {
                    mma8(acc[i][j], ah[i], bl[j]);
                    mma8(acc[i][j], al[i], bh[j]);
                    mma8(acc[i][j], ah[i], bh[j]);
                }
        }
    }

    // epilogue: g row-major (for k_final) + packed A-fragments (for k_cross)
    int rowA = ib * 128, colB = jbD * 128;
#pragma unroll
    for (int i = 0; i < 4; i++) {
#pragma unroll
        for (int half = 0; half < 2; half++) {
            int t = rowA + (wm * 4 + i) * 16 + gr + half * 8;
            int m = t & 127;
            unsigned* pb = P_gA + ((size_t)(t >> 7) * NKT) * SLAI;
#pragma unroll
            for (int j = 0; j < 4; j++) {
                int d = colB + (wn * 4 + j) * 8 + gc * 2;
                float v0 = acc[i][j][half * 2], v1 = acc[i][j][half * 2 + 1];
                *(float2*)&g_g[(size_t)t * DD + d] = make_float2(v0, v1);
                unsigned h0, l0, h1, l1;
                tfsplit(v0, h0, l0);
                tfsplit(v1, h1, l1);
                int kt = d >> 5;
                *(uint2*)&pb[(size_t)kt * SLAI + wA(m, d & 31) * 2]       = make_uint2(h0, l0);
                *(uint2*)&pb[(size_t)kt * SLAI + wA(m, (d + 1) & 31) * 2] = make_uint2(h1, l1);
            }
        }
    }
}

// ---------------- kernel 5: cross = g h^T + fused causal max (3xTF32) ------
__global__ void __launch_bounds__(256) k_cross() {
    __shared__ float red[128 * 4];
    int tid = threadIdx.x, lane = tid & 31, warp = tid >> 5;
    int wm = warp >> 2, wn = warp & 3, gr = lane >> 2, gc = lane & 3;
    int ib, jb;
    triDecode(blockIdx.x, ib, jb);
    int rowA = ib * 128, rowB = jb * 128;

    float acc[4][4][4];
    ACC_INIT(acc)

    const unsigned* Ab = P_gA + (size_t)ib * NKT * SLAI;
    const unsigned* Bhb = P_hBh + (size_t)jb * NKT * SLA;
    const unsigned* Blb = P_hBl + (size_t)jb * NKT * SLA;
#pragma unroll 1
    for (int kt = 0; kt < NKT; kt++) {
        const unsigned* A = Ab + (size_t)kt * SLAI;
        const unsigned* Bh = Bhb + (size_t)kt * SLA;
        const unsigned* Bl = Blb + (size_t)kt * SLA;
#pragma unroll
        for (int ks = 0; ks < 4; ks++) {
            unsigned ah[4][4], al[4][4], bh[4][2], bl[4][2];
#pragma unroll
            for (int i = 0; i < 4; i++) {
                int o = (((wm * 4 + i) * 4 + ks) * 128 + lane * 4) * 2;
                uint4 u0 = *(const uint4*)&A[o];
                uint4 u1 = *(const uint4*)&A[o + 4];
                ah[i][0] = u0.x; al[i][0] = u0.y; ah[i][1] = u0.z; al[i][1] = u0.w;
                ah[i][2] = u1.x; al[i][2] = u1.y; ah[i][3] = u1.z; al[i][3] = u1.w;
            }
#pragma unroll
            for (int j = 0; j < 4; j++) {
                int o = ((wn * 4 + j) * 4 + ks) * 64 + lane * 2;
                *(uint2*)bh[j] = *(const uint2*)&Bh[o];
                *(uint2*)bl[j] = *(const uint2*)&Bl[o];
            }
#pragma unroll
            for (int i = 0; i < 4; i++)
#pragma unroll
                for (int j = 0; j < 4; j++) {
                    mma8(acc[i][j], ah[i], bl[j]);
                    mma8(acc[i][j], al[i], bh[j]);
                    mma8(acc[i][j], ah[i], bh[j]);
                }
        }
    }

    // epilogue: maxQ[t] = max_{s<=t}(hn2[s] - 2*cross[t,s])
    float hn[4][2];
#pragma unroll
    for (int j = 0; j < 4; j++)
#pragma unroll
        for (int e = 0; e < 2; e++)
            hn[j][e] = g_hn2[rowB + (wn * 4 + j) * 8 + gc * 2 + e];

#pragma unroll
    for (int i = 0; i < 4; i++) {
        int rloc = (wm * 4 + i) * 16 + gr;
        int t0 = rowA + rloc;
        float m0 = -3.0e38f, m1 = -3.0e38f;
#pragma unroll
        for (int j = 0; j < 4; j++)
#pragma unroll
            for (int e = 0; e < 2; e++) {
                int s = rowB + (wn * 4 + j) * 8 + gc * 2 + e;
                float q0 = hn[j][e] - 2.0f * acc[i][j][e];
                float q1 = hn[j][e] - 2.0f * acc[i][j][2 + e];
                if (s <= t0)     m0 = fmaxf(m0, q0);
                if (s <= t0 + 8) m1 = fmaxf(m1, q1);
            }
#pragma unroll
        for (int o = 1; o < 4; o <<= 1) {
            m0 = fmaxf(m0, __shfl_xor_sync(0xffffffffu, m0, o));
            m1 = fmaxf(m1, __shfl_xor_sync(0xffffffffu, m1, o));
        }
        if (gc == 0) {
            red[rloc * 4 + wn]       = m0;
            red[(rloc + 8) * 4 + wn] = m1;
        }
    }
    __syncthreads();
    if (tid < 128) {
        float m = fmaxf(fmaxf(red[tid * 4], red[tid * 4 + 1]),
                        fmaxf(red[tid * 4 + 2], red[tid * 4 + 3]));
        if (m > -2.0e38f) atomicMaxF(&g_maxQ[rowA + tid], m);
    }
}

// ---------------- kernel 6: final elementwise ------------------------------
__global__ void k_final(const float* __restrict__ m_t, const float* __restrict__ c_t,
                        const float* __restrict__ d_t, const float* __restrict__ mu,
                        float* __restrict__ out) {
    __shared__ float sh[32];
    int t = blockIdx.x;
    const float* hr = g_h + (size_t)t * DD;
    const float* gr = g_g + (size_t)t * DD;
    float dd = 0.f, gn2 = 0.f;
    for (int i = threadIdx.x; i < DD; i += blockDim.x) {
        float hv = hr[i], gv = gr[i];
        float df = hv - gv;
        dd += df * df;
        gn2 += gv * gv;
    }
    dd = blockReduceSum(dd, sh);
    gn2 = blockReduceSum(gn2, sh);
    if (threadIdx.x == 0) {
        float dist = sqrtf(fmaxf(dd, 1e-24f));
        float dmax = sqrtf(fmaxf(gn2 + g_maxQ[t], 1e-24f));
        if (dmax < 1e-6f) dmax = 1.0f;
        float ratio = dist / (dmax + 1e-8f);
        float stab = 1.0f - 0.3f * c_t[t] + 0.2f * d_t[t];
        float xi = 1.0f - mu[0] * m_t[t];
        float v = ratio * stab * xi;
        out[t] = fminf(fmaxf(v, 0.0f), 1.0f);
    }
}

// ---------------- launch ----------------------------------------------------
extern "C" void kernel_launch(void* const* d_in, const int* in_sizes, int n_in,
                              void* d_out, int out_size) {
    const float* x   = (const float*)d_in[0];
    const float* m_t = (const float*)d_in[1];
    const float* c_t = (const float*)d_in[2];
    const float* d_t = (const float*)d_in[3];
    const float* mu  = (const float*)d_in[4];
    float* out = (float*)d_out;

    k_normalize<<<TT, 256>>>(x);
    k_tables<<<TT / 256, 256>>>();
    k_sim<<<NPAIR, 256>>>();
    k_softmax<<<TT, 256>>>();
    k_g<<<dim3(7, NBLK), 256>>>();
    k_cross<<<NPAIR, 256>>>();
    k_final<<<TT, 256>>>(m_t, c_t, d_t, mu, out);
}

// round 8
// speedup vs baseline: 1.7849x; 1.7849x over previous
#include <cuda_runtime.h>
#include <cstdint>
#include <math.h>

#define TT 4096
#define DD 896

constexpr int BM = 128, BN = 64, BK = 32;
constexpr int NROWB = TT / BM;               // 32 row-blocks of 128
constexpr int NPAIRB = NROWB * (NROWB + 1);  // 1056 causal (128x64) blocks
constexpr int NKT_FULL = DD / BK;            // 28

// packed-stage geometry (padded strides for bank-conflict-free staging)
constexpr int A_GRP = 132;                   // words per (mtile,ks) group (128+4 pad)
constexpr int B_GRP = 68;                    // words per (ntile,ks) group (64+4 pad)
constexpr int A_WORDS = 32 * A_GRP;          // 8 mtiles * 4 ks -> 4224
constexpr int B_WORDS = 32 * B_GRP;          // 8 ntiles * 4 ks -> 2176
constexpr int STAGE1 = A_WORDS + B_WORDS;            // 6400 words (hi only)
constexpr int STAGE3 = 2 * A_WORDS + 2 * B_WORDS;    // 12800 words (hi+lo)
constexpr unsigned DSMEM1 = 2u * STAGE1 * 4u;        // 51200 B
constexpr unsigned DSMEM3 = 2u * STAGE3 * 4u;        // 102400 B

// ---------------- scratch (device globals: allocation-free) ----------------
__device__ float g_h[(size_t)TT * DD];
__device__ float g_g[(size_t)TT * DD];
__device__ float g_sim[(size_t)TT * TT];
__device__ float g_hn2[TT];
__device__ float g_maxQ[TT];
__device__ float g_invden[TT];

// ---------------- small helpers ----------------
__device__ __forceinline__ unsigned f2tf(float f) {
    unsigned u;
    asm("cvt.rna.tf32.f32 %0, %1;" : "=r"(u) : "f"(f));
    return u;
}
__device__ __forceinline__ void tfsplit(float f, unsigned& hi, unsigned& lo) {
    hi = f2tf(f);
    lo = f2tf(f - __uint_as_float(hi));
}
__device__ __forceinline__ void mma8(float* d, const unsigned* a, const unsigned* b) {
    asm volatile(
        "mma.sync.aligned.m16n8k8.row.col.f32.tf32.tf32.f32 "
        "{%0,%1,%2,%3}, {%4,%5,%6,%7}, {%8,%9}, {%0,%1,%2,%3};\n"
        : "+f"(d[0]), "+f"(d[1]), "+f"(d[2]), "+f"(d[3])
        : "r"(a[0]), "r"(a[1]), "r"(a[2]), "r"(a[3]),
          "r"(b[0]), "r"(b[1]));
}
__device__ __forceinline__ float blockReduceSum(float v, float* sh) {
    int lane = threadIdx.x & 31, w = threadIdx.x >> 5;
#pragma unroll
    for (int o = 16; o; o >>= 1) v += __shfl_xor_sync(0xffffffffu, v, o);
    __syncthreads();
    if (lane == 0) sh[w] = v;
    __syncthreads();
    if (threadIdx.x == 0) {
        float s = 0.f;
        int nw = (blockDim.x + 31) >> 5;
        for (int i = 0; i < nw; i++) s += sh[i];
        sh[0] = s;
    }
    __syncthreads();
    return sh[0];
}
__device__ __forceinline__ float blockReduceMax(float v, float* sh) {
    int lane = threadIdx.x & 31, w = threadIdx.x >> 5;
#pragma unroll
    for (int o = 16; o; o >>= 1) v = fmaxf(v, __shfl_xor_sync(0xffffffffu, v, o));
    __syncthreads();
    if (lane == 0) sh[w] = v;
    __syncthreads();
    if (threadIdx.x == 0) {
        float m = -3.0e38f;
        int nw = (blockDim.x + 31) >> 5;
        for (int i = 0; i < nw; i++) m = fmaxf(m, sh[i]);
        sh[0] = m;
    }
    __syncthreads();
    return sh[0];
}
__device__ __forceinline__ void atomicMaxF(float* addr, float val) {
    int old = __float_as_int(*addr);
    while (__int_as_float(old) < val) {
        int assumed = old;
        old = atomicCAS((int*)addr, assumed, __float_as_int(val));
        if (old == assumed) break;
    }
}
// triangular decode for 128x64 causal blocks: ib has 2*ib+2 jb's; cum(ib)=ib*(ib+1)
__device__ __forceinline__ void triDecodeB(int b, int& ib, int& jb) {
    int i = (int)((sqrtf(4.0f * (float)b + 1.0f) - 1.0f) * 0.5f);
    while ((i + 1) * (i + 2) <= b) i++;
    while (i * (i + 1) > b) i--;
    ib = i;
    jb = b - i * (i + 1);
}
__device__ __forceinline__ int bswz(int lane, int grp) { return lane ^ (((grp >> 2) & 7) << 1); }

// ---------------- staging: gmem -> regs -> packed smem ----------------
__device__ __forceinline__ void ldA4(const float* __restrict__ src, int ld, int row0, int k0,
                                     float4* pa, int tid) {
#pragma unroll
    for (int it = 0; it < 4; it++) {
        int idx = tid + it * 256;
        pa[it] = *(const float4*)(src + (size_t)(row0 + (idx >> 3)) * ld + k0 + (idx & 7) * 4);
    }
}
template <bool THREE>
__device__ __forceinline__ void stA4(unsigned* S, const float4* pa, int tid) {
    unsigned* Ah = S;
    unsigned* Al = S + A_WORDS;
#pragma unroll
    for (int it = 0; it < 4; it++) {
        int idx = tid + it * 256;
        int r = idx >> 3, c = (idx & 7) * 4;
        int mt = r >> 4, rr = r & 15, ks = c >> 3;
        int jj = (((c & 7) >= 4) ? 2 : 0) + ((rr >= 8) ? 1 : 0);
        int base = (mt * 4 + ks) * A_GRP + ((rr & 7) << 4) + jj;
        const float* v = (const float*)&pa[it];
#pragma unroll
        for (int q = 0; q < 4; q++) {
            if (THREE) {
                unsigned h, l;
                tfsplit(v[q], h, l);
                Ah[base + q * 4] = h;
                Al[base + q * 4] = l;
            } else {
                Ah[base + q * 4] = f2tf(v[q]);
            }
        }
    }
}
__device__ __forceinline__ void ldBn(const float* __restrict__ src, int ld, int row0, int k0,
                                     float4* pb, int tid) {
#pragma unroll
    for (int it = 0; it < 2; it++) {
        int idx = tid + it * 256;
        pb[it] = *(const float4*)(src + (size_t)(row0 + (idx >> 3)) * ld + k0 + (idx & 7) * 4);
    }
}
template <bool THREE>
__device__ __forceinline__ void stBn(unsigned* S, const float4* pb, int tid) {
    unsigned* Bh = S + (THREE ? 2 * A_WORDS : A_WORDS);
    unsigned* Bl = Bh + B_WORDS;
#pragma unroll
    for (int it = 0; it < 2; it++) {
        int idx = tid + it * 256;
        int n = idx >> 3, c = (idx & 7) * 4;
        int nt = n >> 3, nn = n & 7, ks = c >> 3;
        int jj = ((c & 7) >= 4) ? 1 : 0;
        int grp = nt * 4 + ks;
        const float* v = (const float*)&pb[it];
#pragma unroll
        for (int q = 0; q < 4; q++) {
            int word = grp * B_GRP + (bswz(nn * 4 + q, grp) << 1) + jj;
            if (THREE) {
                unsigned h, l;
                tfsplit(v[q], h, l);
                Bh[word] = h;
                Bl[word] = l;
            } else {
                Bh[word] = f2tf(v[q]);
            }
        }
    }
}
// B[n][k] = g_h[k0+k][colB+n] (transposed read for alpha @ h) — 3x only
__device__ __forceinline__ void ldBk(int k0, int colB, float4* pb, int tid) {
#pragma unroll
    for (int it = 0; it < 2; it++) {
        int idx = tid + it * 256;
        pb[it] = *(const float4*)(g_h + (size_t)(k0 + (idx >> 4)) * DD + colB + (idx & 15) * 4);
    }
}
__device__ __forceinline__ void stBk(unsigned* S, const float4* pb, int tid) {
    unsigned* Bh = S + 2 * A_WORDS;
    unsigned* Bl = Bh + B_WORDS;
#pragma unroll
    for (int it = 0; it < 2; it++) {
        int idx = tid + it * 256;
        int k = idx >> 4, n0 = (idx & 15) * 4;
        int ks = k >> 3, kk = k & 7;
        int jj = (kk >= 4) ? 1 : 0;
        int grp = (n0 >> 3) * 4 + ks;
        const float* v = (const float*)&pb[it];
#pragma unroll
        for (int q = 0; q < 4; q++) {
            int lane = ((n0 + q) & 7) * 4 + (kk & 3);
            int word = grp * B_GRP + (bswz(lane, grp) << 1) + jj;
            unsigned h, l;
            tfsplit(v[q], h, l);
            Bh[word] = h;
            Bl[word] = l;
        }
    }
}

// ---------------- MMA over one staged 32-wide K chunk ----------------------
template <bool THREE>
__device__ __forceinline__ void mma_body(const unsigned* S, float acc[4][2][4],
                                         int wm, int wn, int lane) {
    const unsigned* Ah = S;
    const unsigned* Al = S + A_WORDS;
    const unsigned* Bh = S + (THREE ? 2 * A_WORDS : A_WORDS);
    const unsigned* Bl = Bh + B_WORDS;
#pragma unroll
    for (int ks = 0; ks < 4; ks++) {
        unsigned bh[2][2], bl[2][2];
#pragma unroll
        for (int j = 0; j < 2; j++) {
            int grp = (wn * 2 + j) * 4 + ks;
            int off = grp * B_GRP + (bswz(lane, grp) << 1);
            *(uint2*)bh[j] = *(const uint2*)&Bh[off];
            if (THREE) *(uint2*)bl[j] = *(const uint2*)&Bl[off];
        }
#pragma unroll
        for (int i = 0; i < 4; i++) {
            int offA = ((wm * 4 + i) * 4 + ks) * A_GRP + lane * 4;
            unsigned ah[4], al[4];
            *(uint4*)ah = *(const uint4*)&Ah[offA];
            if (THREE) *(uint4*)al = *(const uint4*)&Al[offA];
#pragma unroll
            for (int j = 0; j < 2; j++) {
                if (THREE) {
                    mma8(acc[i][j], ah, bl[j]);
                    mma8(acc[i][j], al, bh[j]);
                }
                mma8(acc[i][j], ah, bh[j]);
            }
        }
    }
}

#define ACC_INIT(acc)                      \
    _Pragma("unroll")                      \
    for (int i = 0; i < 4; i++)            \
    _Pragma("unroll")                      \
    for (int j = 0; j < 2; j++)            \
    _Pragma("unroll")                      \
    for (int e = 0; e < 4; e++) acc[i][j][e] = 0.f;

// ---------------- kernel 1: normalize rows ----------------
__global__ void k_normalize(const float* __restrict__ x) {
    __shared__ float sh[32];
    int t = blockIdx.x;
    const float* row = x + (size_t)t * DD;
    float ss = 0.f;
    for (int i = threadIdx.x; i < DD; i += blockDim.x) {
        float v = row[i];
        ss += v * v;
    }
    ss = blockReduceSum(ss, sh);
    float inv = 1.0f / fmaxf(sqrtf(ss), 1e-12f);
    float* hr = g_h + (size_t)t * DD;
    for (int i = threadIdx.x; i < DD; i += blockDim.x)
        hr[i] = row[i] * inv;
    if (threadIdx.x == 0) {
        g_hn2[t] = ss * inv * inv;
        g_maxQ[t] = -3.0e38f;
    }
}

__global__ void k_tables() {
    int i = blockIdx.x * 256 + threadIdx.x;
    if (i < TT)
        g_invden[i] = 1.0f / (sqrtf((float)DD) * expf(0.1f * (float)i) + 1e-8f);
}

// ---------------- kernel 2: sim = h h^T (1xTF32, causal 128x64 blocks) -----
__global__ void __launch_bounds__(256, 2) k_sim() {
    extern __shared__ unsigned dsm[];
    int tid = threadIdx.x, lane = tid & 31, warp = tid >> 5;
    int wm = warp >> 2, wn = warp & 3, gr = lane >> 2, gc = lane & 3;
    int ib, jb;
    triDecodeB(blockIdx.x, ib, jb);
    int rowA = ib * BM, rowB = jb * BN;

    float acc[4][2][4];
    ACC_INIT(acc)

    float4 pa[4], pb[2];
    ldA4(g_h, DD, rowA, 0, pa, tid);
    ldBn(g_h, DD, rowB, 0, pb, tid);
    stA4<false>(dsm, pa, tid);
    stBn<false>(dsm, pb, tid);
    ldA4(g_h, DD, rowA, BK, pa, tid);
    ldBn(g_h, DD, rowB, BK, pb, tid);
    __syncthreads();

    for (int kt = 0; kt < NKT_FULL; kt++) {
        if (kt + 1 < NKT_FULL) {
            unsigned* nxt = dsm + ((kt + 1) & 1) * STAGE1;
            stA4<false>(nxt, pa, tid);
            stBn<false>(nxt, pb, tid);
        }
        if (kt + 2 < NKT_FULL) {
            ldA4(g_h, DD, rowA, (kt + 2) * BK, pa, tid);
            ldBn(g_h, DD, rowB, (kt + 2) * BK, pb, tid);
        }
        mma_body<false>(dsm + (kt & 1) * STAGE1, acc, wm, wn, lane);
        __syncthreads();
    }

#pragma unroll
    for (int i = 0; i < 4; i++) {
        int t = rowA + (wm * 4 + i) * 16 + gr;
#pragma unroll
        for (int j = 0; j < 2; j++) {
            int s = rowB + (wn * 2 + j) * 8 + gc * 2;
            *(float2*)&g_sim[(size_t)t * TT + s]       = make_float2(acc[i][j][0], acc[i][j][1]);
            *(float2*)&g_sim[(size_t)(t + 8) * TT + s] = make_float2(acc[i][j][2], acc[i][j][3]);
        }
    }
}

// ---------------- kernel 3: causal decayed softmax per row -----------------
__global__ void k_softmax() {
    __shared__ float sh[32];
    int t = blockIdx.x;
    float* row = g_sim + (size_t)t * TT;
    int n = t + 1;
    float lmax = -3.0e38f;
    for (int s = threadIdx.x; s < n; s += blockDim.x) {
        float l = row[s] * g_invden[t - s];
        row[s] = l;
        lmax = fmaxf(lmax, l);
    }
    lmax = blockReduceMax(lmax, sh);
    float lsum = 0.f;
    for (int s = threadIdx.x; s < n; s += blockDim.x) {
        float e = __expf(row[s] - lmax);
        row[s] = e;
        lsum += e;
    }
    lsum = blockReduceSum(lsum, sh);
    float inv = 1.0f / lsum;
    for (int s = threadIdx.x; s < n; s += blockDim.x) row[s] *= inv;
    int zend = ((t >> 7) + 1) * 128;   // g-GEMM only reads up to block boundary
    for (int s = n + threadIdx.x; s < zend; s += blockDim.x) row[s] = 0.f;
}

// ---------------- kernel 4: g = alpha @ h (3xTF32, causal K-trunc) ---------
__global__ void __launch_bounds__(256, 2) k_g() {
    extern __shared__ unsigned dsm[];
    int tid = threadIdx.x, lane = tid & 31, warp = tid >> 5;
    int wm = warp >> 2, wn = warp & 3, gr = lane >> 2, gc = lane & 3;
    int jbD = blockIdx.x;
    int ib = (NROWB - 1) - blockIdx.y;   // long blocks first
    int rowA = ib * BM, colB = jbD * BN;
    int nkt = (ib + 1) * 4;              // alpha zero beyond causal boundary

    float acc[4][2][4];
    ACC_INIT(acc)

    float4 pa[4], pb[2];
    ldA4(g_sim, TT, rowA, 0, pa, tid);
    ldBk(0, colB, pb, tid);
    stA4<true>(dsm, pa, tid);
    stBk(dsm, pb, tid);
    ldA4(g_sim, TT, rowA, BK, pa, tid);
    ldBk(BK, colB, pb, tid);
    __syncthreads();

    for (int kt = 0; kt < nkt; kt++) {
        if (kt + 1 < nkt) {
            unsigned* nxt = dsm + ((kt + 1) & 1) * STAGE3;
            stA4<true>(nxt, pa, tid);
            stBk(nxt, pb, tid);
        }
        if (kt + 2 < nkt) {
            ldA4(g_sim, TT, rowA, (kt + 2) * BK, pa, tid);
            ldBk((kt + 2) * BK, colB, pb, tid);
        }
        mma_body<true>(dsm + (kt & 1) * STAGE3, acc, wm, wn, lane);
        __syncthreads();
    }

#pragma unroll
    for (int i = 0; i < 4; i++) {
        int t = rowA + (wm * 4 + i) * 16 + gr;
#pragma unroll
        for (int j = 0; j < 2; j++) {
            int d = colB + (wn * 2 + j) * 8 + gc * 2;
            *(float2*)&g_g[(size_t)t * DD + d]       = make_float2(acc[i][j][0], acc[i][j][1]);
            *(float2*)&g_g[(size_t)(t + 8) * DD + d] = make_float2(acc[i][j][2], acc[i][j][3]);
        }
    }
}

// ---------------- kernel 5: cross = g h^T + fused causal max (1xTF32) ------
__global__ void __launch_bounds__(256, 2) k_cross() {
    extern __shared__ unsigned dsm[];
    int tid = threadIdx.x, lane = tid & 31, warp = tid >> 5;
    int wm = warp >> 2, wn = warp & 3, gr = lane >> 2, gc = lane & 3;
    int ib, jb;
    triDecodeB(blockIdx.x, ib, jb);
    int rowA = ib * BM, rowB = jb * BN;

    float acc[4][2][4];
    ACC_INIT(acc)

    float4 pa[4], pb[2];
    ldA4(g_g, DD, rowA, 0, pa, tid);
    ldBn(g_h, DD, rowB, 0, pb, tid);
    stA4<false>(dsm, pa, tid);
    stBn<false>(dsm, pb, tid);
    ldA4(g_g, DD, rowA, BK, pa, tid);
    ldBn(g_h, DD, rowB, BK, pb, tid);
    __syncthreads();

    for (int kt = 0; kt < NKT_FULL; kt++) {
        if (kt + 1 < NKT_FULL) {
            unsigned* nxt = dsm + ((kt + 1) & 1) * STAGE1;
            stA4<false>(nxt, pa, tid);
            stBn<false>(nxt, pb, tid);
        }
        if (kt + 2 < NKT_FULL) {
            ldA4(g_g, DD, rowA, (kt + 2) * BK, pa, tid);
            ldBn(g_h, DD, rowB, (kt + 2) * BK, pb, tid);
        }
        mma_body<false>(dsm + (kt & 1) * STAGE1, acc, wm, wn, lane);
        __syncthreads();
    }

    // epilogue: maxQ[t] = max_{s<=t}(hn2[s] - 2*cross[t,s])
    float hn[2][2];
#pragma unroll
    for (int j = 0; j < 2; j++)
#pragma unroll
        for (int e = 0; e < 2; e++)
            hn[j][e] = g_hn2[rowB + (wn * 2 + j) * 8 + gc * 2 + e];

    float* red = (float*)dsm;   // safe: all MMA reads done (post-loop sync)
#pragma unroll
    for (int i = 0; i < 4; i++) {
        int rloc = (wm * 4 + i) * 16 + gr;
        int t0 = rowA + rloc;
        float m0 = -3.0e38f, m1 = -3.0e38f;
#pragma unroll
        for (int j = 0; j < 2; j++)
#pragma unroll
            for (int e = 0; e < 2; e++) {
                int s = rowB + (wn * 2 + j) * 8 + gc * 2 + e;
                float q0 = hn[j][e] - 2.0f * acc[i][j][e];
                float q1 = hn[j][e] - 2.0f * acc[i][j][2 + e];
                if (s <= t0)     m0 = fmaxf(m0, q0);
                if (s <= t0 + 8) m1 = fmaxf(m1, q1);
            }
#pragma unroll
        for (int o = 1; o < 4; o <<= 1) {
            m0 = fmaxf(m0, __shfl_xor_sync(0xffffffffu, m0, o));
            m1 = fmaxf(m1, __shfl_xor_sync(0xffffffffu, m1, o));
        }
        if (gc == 0) {
            red[rloc * 4 + wn]       = m0;
            red[(rloc + 8) * 4 + wn] = m1;
        }
    }
    __syncthreads();
    if (tid < 128) {
        float m = fmaxf(fmaxf(red[tid * 4], red[tid * 4 + 1]),
                        fmaxf(red[tid * 4 + 2], red[tid * 4 + 3]));
        if (m > -2.0e38f) atomicMaxF(&g_maxQ[rowA + tid], m);
    }
}

// ---------------- kernel 6: final elementwise ------------------------------
__global__ void k_final(const float* __restrict__ m_t, const float* __restrict__ c_t,
                        const float* __restrict__ d_t, const float* __restrict__ mu,
                        float* __restrict__ out) {
    __shared__ float sh[32];
    int t = blockIdx.x;
    const float* hr = g_h + (size_t)t * DD;
    const float* gr = g_g + (size_t)t * DD;
    float dd = 0.f, gn2 = 0.f;
    for (int i = threadIdx.x; i < DD; i += blockDim.x) {
        float hv = hr[i], gv = gr[i];
        float df = hv - gv;
        dd += df * df;
        gn2 += gv * gv;
    }
    dd = blockReduceSum(dd, sh);
    gn2 = blockReduceSum(gn2, sh);
    if (threadIdx.x == 0) {
        float dist = sqrtf(fmaxf(dd, 1e-24f));
        float dmax = sqrtf(fmaxf(gn2 + g_maxQ[t], 1e-24f));
        if (dmax < 1e-6f) dmax = 1.0f;
        float ratio = dist / (dmax + 1e-8f);
        float stab = 1.0f - 0.3f * c_t[t] + 0.2f * d_t[t];
        float xi = 1.0f - mu[0] * m_t[t];
        float v = ratio * stab * xi;
        out[t] = fminf(fmaxf(v, 0.0f), 1.0f);
    }
}

// ---------------- launch ----------------------------------------------------
extern "C" void kernel_launch(void* const* d_in, const int* in_sizes, int n_in,
                              void* d_out, int out_size) {
    const float* x   = (const float*)d_in[0];
    const float* m_t = (const float*)d_in[1];
    const float* c_t = (const float*)d_in[2];
    const float* d_t = (const float*)d_in[3];
    const float* mu  = (const float*)d_in[4];
    float* out = (float*)d_out;

    cudaFuncSetAttribute(k_sim,   cudaFuncAttributeMaxDynamicSharedMemorySize, DSMEM1);
    cudaFuncSetAttribute(k_g,     cudaFuncAttributeMaxDynamicSharedMemorySize, DSMEM3);
    cudaFuncSetAttribute(k_cross, cudaFuncAttributeMaxDynamicSharedMemorySize, DSMEM1);

    k_normalize<<<TT, 256>>>(x);
    k_tables<<<TT / 256, 256>>>();
    k_sim<<<NPAIRB, 256, DSMEM1>>>();
    k_softmax<<<TT, 256>>>();
    k_g<<<dim3(DD / BN, NROWB), 256, DSMEM3>>>();
    k_cross<<<NPAIRB, 256, DSMEM1>>>();
    k_final<<<TT, 256>>>(m_t, c_t, d_t, mu, out);
}

// round 9
// speedup vs baseline: 2.7127x; 1.5198x over previous
#include <cuda_runtime.h>
#include <cuda_bf16.h>
#include <cstdint>
#include <math.h>

#define TT 4096
#define DD 896

constexpr int BM = 128, BN = 64, BK = 32;
constexpr int NROWB = TT / BM;               // 32 row-blocks of 128
constexpr int NPAIRB = NROWB * (NROWB + 1);  // 1056 causal (128x64) blocks
constexpr int NKT_FULL = DD / BK;            // 28

// bf16 packed-stage geometry (1 word = 2 bf16 = one k-pair)
// A: 8 mtiles x 2 ks16-groups = 16 groups, 128 words each (+4 pad)
// B: 8 ntiles x 2 ks16-groups = 16 groups, 64 words each (+4 pad)
constexpr int A_GRP = 132;
constexpr int B_GRP = 68;
constexpr int A_WORDS = 16 * A_GRP;                  // 2112
constexpr int B_WORDS = 16 * B_GRP;                  // 1088
constexpr int STAGE1 = A_WORDS + B_WORDS;            // 3200 words (hi only)
constexpr int STAGE3 = 2 * (A_WORDS + B_WORDS);      // 6400 words (hi+lo)
constexpr unsigned DSMEM1 = 2u * STAGE1 * 4u;        // 25600 B
constexpr unsigned DSMEM3 = 2u * STAGE3 * 4u;        // 51200 B

// ---------------- scratch (device globals: allocation-free) ----------------
__device__ float g_h[(size_t)TT * DD];
__device__ float g_g[(size_t)TT * DD];
__device__ float g_sim[(size_t)TT * TT];
__device__ float g_hn2[TT];
__device__ float g_maxQ[TT];
__device__ float g_invden[TT];

// ---------------- small helpers ----------------
// pack two floats into bf16x2 word: lo -> bits[0:16), hi -> bits[16:32)
__device__ __forceinline__ unsigned pk(float lo, float hi) {
    unsigned r;
    asm("cvt.rn.bf16x2.f32 %0, %1, %2;" : "=r"(r) : "f"(hi), "f"(lo));
    return r;
}
__device__ __forceinline__ void bsplit(float x, float& h, float& l) {
    h = __bfloat162float(__float2bfloat16(x));
    l = x - h;
}
__device__ __forceinline__ void mma16(float* d, const unsigned* a, const unsigned* b) {
    asm volatile(
        "mma.sync.aligned.m16n8k16.row.col.f32.bf16.bf16.f32 "
        "{%0,%1,%2,%3}, {%4,%5,%6,%7}, {%8,%9}, {%0,%1,%2,%3};\n"
        : "+f"(d[0]), "+f"(d[1]), "+f"(d[2]), "+f"(d[3])
        : "r"(a[0]), "r"(a[1]), "r"(a[2]), "r"(a[3]),
          "r"(b[0]), "r"(b[1]));
}
__device__ __forceinline__ float blockReduceSum(float v, float* sh) {
    int lane = threadIdx.x & 31, w = threadIdx.x >> 5;
#pragma unroll
    for (int o = 16; o; o >>= 1) v += __shfl_xor_sync(0xffffffffu, v, o);
    __syncthreads();
    if (lane == 0) sh[w] = v;
    __syncthreads();
    if (threadIdx.x == 0) {
        float s = 0.f;
        int nw = (blockDim.x + 31) >> 5;
        for (int i = 0; i < nw; i++) s += sh[i];
        sh[0] = s;
    }
    __syncthreads();
    return sh[0];
}
__device__ __forceinline__ float blockReduceMax(float v, float* sh) {
    int lane = threadIdx.x & 31, w = threadIdx.x >> 5;
#pragma unroll
    for (int o = 16; o; o >>= 1) v = fmaxf(v, __shfl_xor_sync(0xffffffffu, v, o));
    __syncthreads();
    if (lane == 0) sh[w] = v;
    __syncthreads();
    if (threadIdx.x == 0) {
        float m = -3.0e38f;
        int nw = (blockDim.x + 31) >> 5;
        for (int i = 0; i < nw; i++) m = fmaxf(m, sh[i]);
        sh[0] = m;
    }
    __syncthreads();
    return sh[0];
}
__device__ __forceinline__ void atomicMaxF(float* addr, float val) {
    int old = __float_as_int(*addr);
    while (__int_as_float(old) < val) {
        int assumed = old;
        old = atomicCAS((int*)addr, assumed, __float_as_int(val));
        if (old == assumed) break;
    }
}
__device__ __forceinline__ void triDecodeB(int b, int& ib, int& jb) {
    int i = (int)((sqrtf(4.0f * (float)b + 1.0f) - 1.0f) * 0.5f);
    while ((i + 1) * (i + 2) <= b) i++;
    while (i * (i + 1) > b) i--;
    ib = i;
    jb = b - i * (i + 1);
}

// ---------------- staging: gmem -> regs -> packed bf16 smem ----------------
__device__ __forceinline__ void ldA4(const float* __restrict__ src, int ld, int row0, int k0,
                                     float4* pa, int tid) {
#pragma unroll
    for (int it = 0; it < 4; it++) {
        int idx = tid + it * 256;
        pa[it] = *(const float4*)(src + (size_t)(row0 + (idx >> 3)) * ld + k0 + (idx & 7) * 4);
    }
}
template <bool THREE>
__device__ __forceinline__ void stA4(unsigned* S, const float4* pa, int tid) {
    unsigned* Ah = S;
    unsigned* Al = S + A_WORDS;
#pragma unroll
    for (int it = 0; it < 4; it++) {
        int idx = tid + it * 256;
        int r = idx >> 3, kp0 = (idx & 7) * 2;        // 2 k-pairs per float4
        const float* v = (const float*)&pa[it];
#pragma unroll
        for (int q = 0; q < 2; q++) {
            int kp = kp0 + q, ksg = kp >> 3, kpi = kp & 7;
            int grp = (r >> 4) * 2 + ksg;
            int lane = (r & 7) * 4 + (kpi & 3);
            int j = ((kpi >= 4) ? 2 : 0) + (((r & 15) >= 8) ? 1 : 0);
            int base = grp * A_GRP + lane * 4 + j;
            float v0 = v[q * 2], v1 = v[q * 2 + 1];
            if (THREE) {
                float h0, l0, h1, l1;
                bsplit(v0, h0, l0);
                bsplit(v1, h1, l1);
                Ah[base] = pk(h0, h1);
                Al[base] = pk(l0, l1);
            } else {
                Ah[base] = pk(v0, v1);
            }
        }
    }
}
__device__ __forceinline__ void ldBn(const float* __restrict__ src, int ld, int row0, int k0,
                                     float4* pb, int tid) {
#pragma unroll
    for (int it = 0; it < 2; it++) {
        int idx = tid + it * 256;
        pb[it] = *(const float4*)(src + (size_t)(row0 + (idx >> 3)) * ld + k0 + (idx & 7) * 4);
    }
}
template <bool THREE>
__device__ __forceinline__ void stBn(unsigned* S, const float4* pb, int tid) {
    unsigned* Bh = S + (THREE ? 2 * A_WORDS : A_WORDS);
    unsigned* Bl = Bh + B_WORDS;
#pragma unroll
    for (int it = 0; it < 2; it++) {
        int idx = tid + it * 256;
        int n = idx >> 3, kp0 = (idx & 7) * 2;
        const float* v = (const float*)&pb[it];
#pragma unroll
        for (int q = 0; q < 2; q++) {
            int kp = kp0 + q, ksg = kp >> 3, kpi = kp & 7;
            int grp = (n >> 3) * 2 + ksg;
            int lane = (n & 7) * 4 + (kpi & 3);
            int word = grp * B_GRP + lane * 2 + (kpi >= 4 ? 1 : 0);
            float v0 = v[q * 2], v1 = v[q * 2 + 1];
            if (THREE) {
                float h0, l0, h1, l1;
                bsplit(v0, h0, l0);
                bsplit(v1, h1, l1);
                Bh[word] = pk(h0, h1);
                Bl[word] = pk(l0, l1);
            } else {
                Bh[word] = pk(v0, v1);
            }
        }
    }
}
// transposed B for alpha @ h: B[n][k] = g_h[k0+k][colB+n] (3x, hi/lo)
__device__ __forceinline__ void ldBk(int k0, int colB, float4* pb, int tid) {
    int kp = tid >> 4, n0 = (tid & 15) * 4;
    pb[0] = *(const float4*)(g_h + (size_t)(k0 + 2 * kp) * DD + colB + n0);
    pb[1] = *(const float4*)(g_h + (size_t)(k0 + 2 * kp + 1) * DD + colB + n0);
}
__device__ __forceinline__ void stBk(unsigned* S, const float4* pb, int tid) {
    unsigned* Bh = S + 2 * A_WORDS;
    unsigned* Bl = Bh + B_WORDS;
    int kp = tid >> 4, n0 = (tid & 15) * 4;
    int ksg = kp >> 3, kpi = kp & 7;
    const float* v0 = (const float*)&pb[0];   // k = 2kp
    const float* v1 = (const float*)&pb[1];   // k = 2kp+1
#pragma unroll
    for (int q = 0; q < 4; q++) {
        int n = n0 + q;
        int grp = (n >> 3) * 2 + ksg;
        int lane = (n & 7) * 4 + (kpi & 3);
        int word = grp * B_GRP + lane * 2 + (kpi >= 4 ? 1 : 0);
        float h0, l0, h1, l1;
        bsplit(v0[q], h0, l0);
        bsplit(v1[q], h1, l1);
        Bh[word] = pk(h0, h1);
        Bl[word] = pk(l0, l1);
    }
}

// ---------------- MMA over one staged 32-wide K chunk ----------------------
template <bool THREE>
__device__ __forceinline__ void mma_body(const unsigned* S, float acc[4][2][4],
                                         int wm, int wn, int lane) {
    const unsigned* Ah = S;
    const unsigned* Al = S + A_WORDS;
    const unsigned* Bh = S + (THREE ? 2 * A_WORDS : A_WORDS);
    const unsigned* Bl = Bh + B_WORDS;
#pragma unroll
    for (int ksg = 0; ksg < 2; ksg++) {
        unsigned bh[2][2], bl[2][2];
#pragma unroll
        for (int j = 0; j < 2; j++) {
            int off = ((wn * 2 + j) * 2 + ksg) * B_GRP + lane * 2;
            *(uint2*)bh[j] = *(const uint2*)&Bh[off];
            if (THREE) *(uint2*)bl[j] = *(const uint2*)&Bl[off];
        }
#pragma unroll
        for (int i = 0; i < 4; i++) {
            int offA = ((wm * 4 + i) * 2 + ksg) * A_GRP + lane * 4;
            unsigned ah[4], al[4];
            *(uint4*)ah = *(const uint4*)&Ah[offA];
            if (THREE) *(uint4*)al = *(const uint4*)&Al[offA];
#pragma unroll
            for (int j = 0; j < 2; j++) {
                if (THREE) {
                    mma16(acc[i][j], ah, bl[j]);
                    mma16(acc[i][j], al, bh[j]);
                }
                mma16(acc[i][j], ah, bh[j]);
            }
        }
    }
}

#define ACC_INIT(acc)                      \
    _Pragma("unroll")                      \
    for (int i = 0; i < 4; i++)            \
    _Pragma("unroll")                      \
    for (int j = 0; j < 2; j++)            \
    _Pragma("unroll")                      \
    for (int e = 0; e < 4; e++) acc[i][j][e] = 0.f;

// ---------------- kernel 1: normalize rows ----------------
__global__ void k_normalize(const float* __restrict__ x) {
    __shared__ float sh[32];
    int t = blockIdx.x;
    const float* row = x + (size_t)t * DD;
    float ss = 0.f;
    for (int i = threadIdx.x; i < DD; i += blockDim.x) {
        float v = row[i];
        ss += v * v;
    }
    ss = blockReduceSum(ss, sh);
    float inv = 1.0f / fmaxf(sqrtf(ss), 1e-12f);
    float* hr = g_h + (size_t)t * DD;
    for (int i = threadIdx.x; i < DD; i += blockDim.x)
        hr[i] = row[i] * inv;
    if (threadIdx.x == 0) {
        g_hn2[t] = ss * inv * inv;
        g_maxQ[t] = -3.0e38f;
    }
}

__global__ void k_tables() {
    int i = blockIdx.x * 256 + threadIdx.x;
    if (i < TT)
        g_invden[i] = 1.0f / (sqrtf((float)DD) * expf(0.1f * (float)i) + 1e-8f);
}

// ---------------- kernel 2: sim = h h^T (1xBF16, causal 128x64 blocks) -----
__global__ void __launch_bounds__(256, 2) k_sim() {
    extern __shared__ unsigned dsm[];
    int tid = threadIdx.x, lane = tid & 31, warp = tid >> 5;
    int wm = warp >> 2, wn = warp & 3, gr = lane >> 2, gc = lane & 3;
    int ib, jb;
    triDecodeB(blockIdx.x, ib, jb);
    int rowA = ib * BM, rowB = jb * BN;

    float acc[4][2][4];
    ACC_INIT(acc)

    float4 pa[4], pb[2];
    ldA4(g_h, DD, rowA, 0, pa, tid);
    ldBn(g_h, DD, rowB, 0, pb, tid);
    stA4<false>(dsm, pa, tid);
    stBn<false>(dsm, pb, tid);
    ldA4(g_h, DD, rowA, BK, pa, tid);
    ldBn(g_h, DD, rowB, BK, pb, tid);
    __syncthreads();

    for (int kt = 0; kt < NKT_FULL; kt++) {
        if (kt + 1 < NKT_FULL) {
            unsigned* nxt = dsm + ((kt + 1) & 1) * STAGE1;
            stA4<false>(nxt, pa, tid);
            stBn<false>(nxt, pb, tid);
        }
        if (kt + 2 < NKT_FULL) {
            ldA4(g_h, DD, rowA, (kt + 2) * BK, pa, tid);
            ldBn(g_h, DD, rowB, (kt + 2) * BK, pb, tid);
        }
        mma_body<false>(dsm + (kt & 1) * STAGE1, acc, wm, wn, lane);
        __syncthreads();
    }

#pragma unroll
    for (int i = 0; i < 4; i++) {
        int t = rowA + (wm * 4 + i) * 16 + gr;
#pragma unroll
        for (int j = 0; j < 2; j++) {
            int s = rowB + (wn * 2 + j) * 8 + gc * 2;
            *(float2*)&g_sim[(size_t)t * TT + s]       = make_float2(acc[i][j][0], acc[i][j][1]);
            *(float2*)&g_sim[(size_t)(t + 8) * TT + s] = make_float2(acc[i][j][2], acc[i][j][3]);
        }
    }
}

// ---------------- kernel 3: causal decayed softmax per row -----------------
__global__ void k_softmax() {
    __shared__ float sh[32];
    int t = blockIdx.x;
    float* row = g_sim + (size_t)t * TT;
    int n = t + 1;
    float lmax = -3.0e38f;
    for (int s = threadIdx.x; s < n; s += blockDim.x) {
        float l = row[s] * g_invden[t - s];
        row[s] = l;
        lmax = fmaxf(lmax, l);
    }
    lmax = blockReduceMax(lmax, sh);
    float lsum = 0.f;
    for (int s = threadIdx.x; s < n; s += blockDim.x) {
        float e = __expf(row[s] - lmax);
        row[s] = e;
        lsum += e;
    }
    lsum = blockReduceSum(lsum, sh);
    float inv = 1.0f / lsum;
    for (int s = threadIdx.x; s < n; s += blockDim.x) row[s] *= inv;
    int zend = ((t >> 7) + 1) * 128;   // g-GEMM only reads up to block boundary
    for (int s = n + threadIdx.x; s < zend; s += blockDim.x) row[s] = 0.f;
}

// ---------------- kernel 4: g = alpha @ h (3xBF16, causal K-trunc) ---------
__global__ void __launch_bounds__(256, 2) k_g() {
    extern __shared__ unsigned dsm[];
    int tid = threadIdx.x, lane = tid & 31, warp = tid >> 5;
    int wm = warp >> 2, wn = warp & 3, gr = lane >> 2, gc = lane & 3;
    int jbD = blockIdx.x;
    int ib = (NROWB - 1) - blockIdx.y;   // long blocks first
    int rowA = ib * BM, colB = jbD * BN;
    int nkt = (ib + 1) * 4;              // alpha zero beyond causal boundary

    float acc[4][2][4];
    ACC_INIT(acc)

    float4 pa[4], pb[2];
    ldA4(g_sim, TT, rowA, 0, pa, tid);
    ldBk(0, colB, pb, tid);
    stA4<true>(dsm, pa, tid);
    stBk(dsm, pb, tid);
    ldA4(g_sim, TT, rowA, BK, pa, tid);
    ldBk(BK, colB, pb, tid);
    __syncthreads();

    for (int kt = 0; kt < nkt; kt++) {
        if (kt + 1 < nkt) {
            unsigned* nxt = dsm + ((kt + 1) & 1) * STAGE3;
            stA4<true>(nxt, pa, tid);
            stBk(nxt, pb, tid);
        }
        if (kt + 2 < nkt) {
            ldA4(g_sim, TT, rowA, (kt + 2) * BK, pa, tid);
            ldBk((kt + 2) * BK, colB, pb, tid);
        }
        mma_body<true>(dsm + (kt & 1) * STAGE3, acc, wm, wn, lane);
        __syncthreads();
    }

#pragma unroll
    for (int i = 0; i < 4; i++) {
        int t = rowA + (wm * 4 + i) * 16 + gr;
#pragma unroll
        for (int j = 0; j < 2; j++) {
            int d = colB + (wn * 2 + j) * 8 + gc * 2;
            *(float2*)&g_g[(size_t)t * DD + d]       = make_float2(acc[i][j][0], acc[i][j][1]);
            *(float2*)&g_g[(size_t)(t + 8) * DD + d] = make_float2(acc[i][j][2], acc[i][j][3]);
        }
    }
}

// ---------------- kernel 5: cross = g h^T + fused causal max (1xBF16) ------
__global__ void __launch_bounds__(256, 2) k_cross() {
    extern __shared__ unsigned dsm[];
    int tid = threadIdx.x, lane = tid & 31, warp = tid >> 5;
    int wm = warp >> 2, wn = warp & 3, gr = lane >> 2, gc = lane & 3;
    int ib, jb;
    triDecodeB(blockIdx.x, ib, jb);
    int rowA = ib * BM, rowB = jb * BN;

    float acc[4][2][4];
    ACC_INIT(acc)

    float4 pa[4], pb[2];
    ldA4(g_g, DD, rowA, 0, pa, tid);
    ldBn(g_h, DD, rowB, 0, pb, tid);
    stA4<false>(dsm, pa, tid);
    stBn<false>(dsm, pb, tid);
    ldA4(g_g, DD, rowA, BK, pa, tid);
    ldBn(g_h, DD, rowB, BK, pb, tid);
    __syncthreads();

    for (int kt = 0; kt < NKT_FULL; kt++) {
        if (kt + 1 < NKT_FULL) {
            unsigned* nxt = dsm + ((kt + 1) & 1) * STAGE1;
            stA4<false>(nxt, pa, tid);
            stBn<false>(nxt, pb, tid);
        }
        if (kt + 2 < NKT_FULL) {
            ldA4(g_g, DD, rowA, (kt + 2) * BK, pa, tid);
            ldBn(g_h, DD, rowB, (kt + 2) * BK, pb, tid);
        }
        mma_body<false>(dsm + (kt & 1) * STAGE1, acc, wm, wn, lane);
        __syncthreads();
    }

    // epilogue: maxQ[t] = max_{s<=t}(hn2[s] - 2*cross[t,s])
    float hn[2][2];
#pragma unroll
    for (int j = 0; j < 2; j++)
#pragma unroll
        for (int e = 0; e < 2; e++)
            hn[j][e] = g_hn2[rowB + (wn * 2 + j) * 8 + gc * 2 + e];

    float* red = (float*)dsm;   // safe: all MMA reads done (post-loop sync)
#pragma unroll
    for (int i = 0; i < 4; i++) {
        int rloc = (wm * 4 + i) * 16 + gr;
        int t0 = rowA + rloc;
        float m0 = -3.0e38f, m1 = -3.0e38f;
#pragma unroll
        for (int j = 0; j < 2; j++)
#pragma unroll
            for (int e = 0; e < 2; e++) {
                int s = rowB + (wn * 2 + j) * 8 + gc * 2 + e;
                float q0 = hn[j][e] - 2.0f * acc[i][j][e];
                float q1 = hn[j][e] - 2.0f * acc[i][j][2 + e];
                if (s <= t0)     m0 = fmaxf(m0, q0);
                if (s <= t0 + 8) m1 = fmaxf(m1, q1);
            }
#pragma unroll
        for (int o = 1; o < 4; o <<= 1) {
            m0 = fmaxf(m0, __shfl_xor_sync(0xffffffffu, m0, o));
            m1 = fmaxf(m1, __shfl_xor_sync(0xffffffffu, m1, o));
        }
        if (gc == 0) {
            red[rloc * 4 + wn]       = m0;
            red[(rloc + 8) * 4 + wn] = m1;
        }
    }
    __syncthreads();
    if (tid < 128) {
        float m = fmaxf(fmaxf(red[tid * 4], red[tid * 4 + 1]),
                        fmaxf(red[tid * 4 + 2], red[tid * 4 + 3]));
        if (m > -2.0e38f) atomicMaxF(&g_maxQ[rowA + tid], m);
    }
}

// ---------------- kernel 6: final elementwise ------------------------------
__global__ void k_final(const float* __restrict__ m_t, const float* __restrict__ c_t,
                        const float* __restrict__ d_t, const float* __restrict__ mu,
                        float* __restrict__ out) {
    __shared__ float sh[32];
    int t = blockIdx.x;
    const float* hr = g_h + (size_t)t * DD;
    const float* gr = g_g + (size_t)t * DD;
    float dd = 0.f, gn2 = 0.f;
    for (int i = threadIdx.x; i < DD; i += blockDim.x) {
        float hv = hr[i], gv = gr[i];
        float df = hv - gv;
        dd += df * df;
        gn2 += gv * gv;
    }
    dd = blockReduceSum(dd, sh);
    gn2 = blockReduceSum(gn2, sh);
    if (threadIdx.x == 0) {
        float dist = sqrtf(fmaxf(dd, 1e-24f));
        float dmax = sqrtf(fmaxf(gn2 + g_maxQ[t], 1e-24f));
        if (dmax < 1e-6f) dmax = 1.0f;
        float ratio = dist / (dmax + 1e-8f);
        float stab = 1.0f - 0.3f * c_t[t] + 0.2f * d_t[t];
        float xi = 1.0f - mu[0] * m_t[t];
        float v = ratio * stab * xi;
        out[t] = fminf(fmaxf(v, 0.0f), 1.0f);
    }
}

// ---------------- launch ----------------------------------------------------
extern "C" void kernel_launch(void* const* d_in, const int* in_sizes, int n_in,
                              void* d_out, int out_size) {
    const float* x   = (const float*)d_in[0];
    const float* m_t = (const float*)d_in[1];
    const float* c_t = (const float*)d_in[2];
    const float* d_t = (const float*)d_in[3];
    const float* mu  = (const float*)d_in[4];
    float* out = (float*)d_out;

    cudaFuncSetAttribute(k_g, cudaFuncAttributeMaxDynamicSharedMemorySize, DSMEM3);

    k_normalize<<<TT, 256>>>(x);
    k_tables<<<TT / 256, 256>>>();
    k_sim<<<NPAIRB, 256, DSMEM1>>>();
    k_softmax<<<TT, 256>>>();
    k_g<<<dim3(DD / BN, NROWB), 256, DSMEM3>>>();
    k_cross<<<NPAIRB, 256, DSMEM1>>>();
    k_final<<<TT, 256>>>(m_t, c_t, d_t, mu, out);
}

// round 11
// speedup vs baseline: 3.0289x; 1.1166x over previous
#include <cuda_runtime.h>
#include <cuda_bf16.h>
#include <cstdint>
#include <math.h>

#define TT 4096
#define DD 896

constexpr int BM = 128, BN = 64, BK = 32;
constexpr int NROWB = TT / BM;               // 32 row-blocks of 128
constexpr int NNB   = TT / BN;               // 64 n-blocks of 64
constexpr int NPAIRB = NROWB * (NROWB + 1);  // 1056 causal (128x64) blocks
constexpr int NKT_FULL = DD / BK;            // 28
constexpr int NKT_T = TT / BK;               // 128 (k over T, for g)
constexpr int NDB = DD / BN;                 // 14 d-blocks

// fragment slab sizes in 32-bit words (1 word = 2 bf16 = one k-pair)
constexpr int A_SLAB = 2048;                 // 128 x 32 bf16
constexpr int B_SLAB = 1024;                 // 64 x 32 bf16
constexpr int STAGE1 = A_SLAB + B_SLAB;              // 3072 words
constexpr int STAGE3 = 2 * A_SLAB + 2 * B_SLAB;      // 6144 words
constexpr unsigned DSMEM1 = 2u * STAGE1 * 4u;        // 24576 B
constexpr unsigned DSMEM3 = 2u * STAGE3 * 4u;        // 49152 B

// ---------------- scratch (device globals: allocation-free) ----------------
__device__ float g_h[(size_t)TT * DD];
__device__ float g_g[(size_t)TT * DD];
__device__ float g_sim[(size_t)TT * TT];
__device__ float g_hn2[TT];
__device__ float g_maxQ[TT];
__device__ float g_invden[TT];

// pre-packed bf16 fragment tables (written by producers, memcpy'd by GEMMs)
__device__ unsigned T_hA [(size_t)NROWB * NKT_FULL * A_SLAB];  // h, A-layout hi
__device__ unsigned T_hB [(size_t)NNB   * NKT_FULL * B_SLAB];  // h, B n-major hi
__device__ unsigned T_hTh[(size_t)NDB   * NKT_T    * B_SLAB];  // h^T, B k-major hi
__device__ unsigned T_hTl[(size_t)NDB   * NKT_T    * B_SLAB];  // lo
__device__ unsigned T_aAh[(size_t)NROWB * NKT_T    * A_SLAB];  // alpha, A-layout hi
__device__ unsigned T_aAl[(size_t)NROWB * NKT_T    * A_SLAB];  // lo
__device__ unsigned T_gA [(size_t)NROWB * NKT_FULL * A_SLAB];  // g, A-layout hi

// ---------------- small helpers ----------------
__device__ __forceinline__ unsigned pk(float lo, float hi) {
    unsigned r;
    asm("cvt.rn.bf16x2.f32 %0, %1, %2;" : "=r"(r) : "f"(hi), "f"(lo));
    return r;
}
__device__ __forceinline__ void bsplit(float x, float& h, float& l) {
    h = __bfloat162float(__float2bfloat16(x));
    l = x - h;
}
__device__ __forceinline__ void mma16(float* d, const unsigned* a, const unsigned* b) {
    asm volatile(
        "mma.sync.aligned.m16n8k16.row.col.f32.bf16.bf16.f32 "
        "{%0,%1,%2,%3}, {%4,%5,%6,%7}, {%8,%9}, {%0,%1,%2,%3};\n"
        : "+f"(d[0]), "+f"(d[1]), "+f"(d[2]), "+f"(d[3])
        : "r"(a[0]), "r"(a[1]), "r"(a[2]), "r"(a[3]),
          "r"(b[0]), "r"(b[1]));
}
// fragment word index within an A slab (m in 0..127, kp = k-pair in 0..15)
__device__ __forceinline__ int wordA(int m, int kp) {
    int grp = (m >> 4) * 2 + (kp >> 3);
    int lane = (m & 7) * 4 + (kp & 3);
    int j = (((kp & 7) >= 4) ? 2 : 0) + (((m & 15) >= 8) ? 1 : 0);
    return grp * 128 + lane * 4 + j;
}
// fragment word index within a B slab (n in 0..63, kp in 0..15)
__device__ __forceinline__ int wordB(int n, int kp) {
    int grp = (n >> 3) * 2 + (kp >> 3);
    int lane = (n & 7) * 4 + (kp & 3);
    int j = ((kp & 7) >= 4) ? 1 : 0;
    return grp * 64 + lane * 2 + j;
}
__device__ __forceinline__ float blockReduceSum(float v, float* sh) {
    int lane = threadIdx.x & 31, w = threadIdx.x >> 5;
#pragma unroll
    for (int o = 16; o; o >>= 1) v += __shfl_xor_sync(0xffffffffu, v, o);
    __syncthreads();
    if (lane == 0) sh[w] = v;
    __syncthreads();
    if (threadIdx.x == 0) {
        float s = 0.f;
        int nw = (blockDim.x + 31) >> 5;
        for (int i = 0; i < nw; i++) s += sh[i];
        sh[0] = s;
    }
    __syncthreads();
    return sh[0];
}
__device__ __forceinline__ float blockReduceMax(float v, float* sh) {
    int lane = threadIdx.x & 31, w = threadIdx.x >> 5;
#pragma unroll
    for (int o = 16; o; o >>= 1) v = fmaxf(v, __shfl_xor_sync(0xffffffffu, v, o));
    __syncthreads();
    if (lane == 0) sh[w] = v;
    __syncthreads();
    if (threadIdx.x == 0) {
        float m = -3.0e38f;
        int nw = (blockDim.x + 31) >> 5;
        for (int i = 0; i < nw; i++) m = fmaxf(m, sh[i]);
        sh[0] = m;
    }
    __syncthreads();
    return sh[0];
}
__device__ __forceinline__ void atomicMaxF(float* addr, float val) {
    int old = __float_as_int(*addr);
    while (__int_as_float(old) < val) {
        int assumed = old;
        old = atomicCAS((int*)addr, assumed, __float_as_int(val));
        if (old == assumed) break;
    }
}
__device__ __forceinline__ void triDecodeB(int b, int& ib, int& jb) {
    int i = (int)((sqrtf(4.0f * (float)b + 1.0f) - 1.0f) * 0.5f);
    while ((i + 1) * (i + 2) <= b) i++;
    while (i * (i + 1) > b) i--;
    ib = i;
    jb = b - i * (i + 1);
}

// ---------------- MMA over one staged 32-wide K chunk ----------------------
template <bool THREE>
__device__ __forceinline__ void mma_body(const unsigned* S, float acc[4][2][4],
                                         int wm, int wn, int lane) {
    const unsigned* Ah = S;
    const unsigned* Al = S + A_SLAB;
    const unsigned* Bh = S + (THREE ? 2 * A_SLAB : A_SLAB);
    const unsigned* Bl = Bh + B_SLAB;
#pragma unroll
    for (int ksg = 0; ksg < 2; ksg++) {
        unsigned bh[2][2], bl[2][2];
#pragma unroll
        for (int j = 0; j < 2; j++) {
            int off = ((wn * 2 + j) * 2 + ksg) * 64 + lane * 2;
            *(uint2*)bh[j] = *(const uint2*)&Bh[off];
            if (THREE) *(uint2*)bl[j] = *(const uint2*)&Bl[off];
        }
#pragma unroll
        for (int i = 0; i < 4; i++) {
            int offA = ((wm * 4 + i) * 2 + ksg) * 128 + lane * 4;
            unsigned ah[4], al[4];
            *(uint4*)ah = *(const uint4*)&Ah[offA];
            if (THREE) *(uint4*)al = *(const uint4*)&Al[offA];
#pragma unroll
            for (int j = 0; j < 2; j++) {
                if (THREE) {
                    mma16(acc[i][j], ah, bl[j]);
                    mma16(acc[i][j], al, bh[j]);
                }
                mma16(acc[i][j], ah, bh[j]);
            }
        }
    }
}

#define ACC_INIT(acc)                      \
    _Pragma("unroll")                      \
    for (int i = 0; i < 4; i++)            \
    _Pragma("unroll")                      \
    for (int j = 0; j < 2; j++)            \
    _Pragma("unroll")                      \
    for (int e = 0; e < 4; e++) acc[i][j][e] = 0.f;

// ---------------- kernel 1: normalize + pack h (A-layout, B n-major) -------
__global__ void k_normalize(const float* __restrict__ x) {
    __shared__ float sh[32];
    int t = blockIdx.x;
    const float* row = x + (size_t)t * DD;
    float ss = 0.f;
    for (int i = threadIdx.x; i < DD; i += blockDim.x) {
        float v = row[i];
        ss += v * v;
    }
    ss = blockReduceSum(ss, sh);
    float inv = 1.0f / fmaxf(sqrtf(ss), 1e-12f);
    float* hr = g_h + (size_t)t * DD;
    int mA = t & 127, nB = t & 63;
    size_t baseA = ((size_t)(t >> 7) * NKT_FULL) * A_SLAB;
    size_t baseB = ((size_t)(t >> 6) * NKT_FULL) * B_SLAB;
    for (int dp = threadIdx.x; dp < DD / 2; dp += blockDim.x) {
        int d = dp * 2;
        float v0 = row[d] * inv, v1 = row[d + 1] * inv;
        hr[d] = v0;
        hr[d + 1] = v1;
        int kt = dp >> 4, kpl = dp & 15;
        unsigned w = pk(v0, v1);
        T_hA[baseA + (size_t)kt * A_SLAB + wordA(mA, kpl)] = w;
        T_hB[baseB + (size_t)kt * B_SLAB + wordB(nB, kpl)] = w;
    }
    if (threadIdx.x == 0) {
        g_hn2[t] = ss * inv * inv;
        g_maxQ[t] = -3.0e38f;
    }
}

// ---------------- kernel 1b: pack h^T (B k-major, hi+lo) for g-GEMM --------
__global__ void k_packT() {
    __shared__ float sm[32][65];
    int jb = blockIdx.x;      // d-block (64 wide)
    int kt = blockIdx.y;      // t-chunk (32 tall)
    int tid = threadIdx.x;
#pragma unroll
    for (int it = 0; it < 8; it++) {
        int e = tid + it * 256;
        int tl = e >> 6, dl = e & 63;
        sm[tl][dl] = g_h[(size_t)(kt * 32 + tl) * DD + jb * 64 + dl];
    }
    __syncthreads();
    size_t base = ((size_t)jb * NKT_T + kt) * B_SLAB;
#pragma unroll
    for (int it = 0; it < 4; it++) {
        int w = tid + it * 256;
        int grp = w >> 6, rem = w & 63;
        int lane = rem >> 1, j = rem & 1;
        int n = (grp >> 1) * 8 + (lane >> 2);
        int kp = (grp & 1) * 8 + j * 4 + (lane & 3);
        float h0, l0, h1, l1;
        bsplit(sm[2 * kp][n], h0, l0);
        bsplit(sm[2 * kp + 1][n], h1, l1);
        T_hTh[base + w] = pk(h0, h1);
        T_hTl[base + w] = pk(l0, l1);
    }
}

__global__ void k_tables() {
    int i = blockIdx.x * 256 + threadIdx.x;
    if (i < TT)
        g_invden[i] = 1.0f / (sqrtf((float)DD) * expf(0.1f * (float)i) + 1e-8f);
}

// ---------------- kernel 2: sim = h h^T (1xBF16, copy-staged) --------------
__global__ void __launch_bounds__(256, 2) k_sim() {
    extern __shared__ unsigned dsm[];
    int tid = threadIdx.x, lane = tid & 31, warp = tid >> 5;
    int wm = warp >> 2, wn = warp & 3, gr = lane >> 2, gc = lane & 3;
    int ib, jb;
    triDecodeB(blockIdx.x, ib, jb);
    int rowA = ib * BM, rowB = jb * BN;

    float acc[4][2][4];
    ACC_INIT(acc)

    const uint4* A4 = (const uint4*)(T_hA + ((size_t)ib * NKT_FULL) * A_SLAB);
    const uint4* B4 = (const uint4*)(T_hB + ((size_t)jb * NKT_FULL) * B_SLAB);
    constexpr int A4W = A_SLAB / 4, B4W = B_SLAB / 4;   // 512, 256 uint4/slab

    uint4 pa0, pa1, pb0;
    pa0 = A4[tid]; pa1 = A4[tid + 256]; pb0 = B4[tid];
    {
        uint4* S4 = (uint4*)dsm;
        S4[tid] = pa0; S4[tid + 256] = pa1; S4[512 + tid] = pb0;
    }
    pa0 = A4[A4W + tid]; pa1 = A4[A4W + tid + 256]; pb0 = B4[B4W + tid];
    __syncthreads();

    for (int kt = 0; kt < NKT_FULL; kt++) {
        if (kt + 1 < NKT_FULL) {
            uint4* S4 = (uint4*)(dsm + ((kt + 1) & 1) * STAGE1);
            S4[tid] = pa0; S4[tid + 256] = pa1; S4[512 + tid] = pb0;
        }
        if (kt + 2 < NKT_FULL) {
            pa0 = A4[(size_t)(kt + 2) * A4W + tid];
            pa1 = A4[(size_t)(kt + 2) * A4W + tid + 256];
            pb0 = B4[(size_t)(kt + 2) * B4W + tid];
        }
        mma_body<false>(dsm + (kt & 1) * STAGE1, acc, wm, wn, lane);
        __syncthreads();
    }

#pragma unroll
    for (int i = 0; i < 4; i++) {
        int t = rowA + (wm * 4 + i) * 16 + gr;
#pragma unroll
        for (int j = 0; j < 2; j++) {
            int s = rowB + (wn * 2 + j) * 8 + gc * 2;
            *(float2*)&g_sim[(size_t)t * TT + s]       = make_float2(acc[i][j][0], acc[i][j][1]);
            *(float2*)&g_sim[(size_t)(t + 8) * TT + s] = make_float2(acc[i][j][2], acc[i][j][3]);
        }
    }
}

// ---------------- kernel 3: softmax -> packed alpha fragments (hi/lo) ------
__global__ void k_softmax() {
    __shared__ float sh[32];
    int t = blockIdx.x;
    float* row = g_sim + (size_t)t * TT;
    int n = t + 1;
    float lmax = -3.0e38f;
    for (int s = threadIdx.x; s < n; s += blockDim.x) {
        float l = row[s] * g_invden[t - s];
        row[s] = l;
        lmax = fmaxf(lmax, l);
    }
    lmax = blockReduceMax(lmax, sh);
    float lsum = 0.f;
    for (int s = threadIdx.x; s < n; s += blockDim.x) {
        float e = __expf(row[s] - lmax);
        row[s] = e;
        lsum += e;
    }
    lsum = blockReduceSum(lsum, sh);
    float inv = 1.0f / lsum;

    int ib = t >> 7, m = t & 127;
    size_t base = ((size_t)ib * NKT_T) * A_SLAB;
    int npairs = (ib + 1) * 64;             // zend/2, covers kt < (ib+1)*4
    for (int sp = threadIdx.x; sp < npairs; sp += blockDim.x) {
        int s0 = 2 * sp, s1 = s0 + 1;
        float v0 = (s0 <= t) ? row[s0] * inv : 0.f;
        float v1 = (s1 <= t) ? row[s1] * inv : 0.f;
        float h0, l0, h1, l1;
        bsplit(v0, h0, l0);
        bsplit(v1, h1, l1);
        size_t idx = base + (size_t)(sp >> 4) * A_SLAB + wordA(m, sp & 15);
        T_aAh[idx] = pk(h0, h1);
        T_aAl[idx] = pk(l0, l1);
    }
}

// ---------------- kernel 4: g = alpha @ h (3xBF16, copy-staged) ------------
__global__ void __launch_bounds__(256, 2) k_g() {
    extern __shared__ unsigned dsm[];
    int tid = threadIdx.x, lane = tid & 31, warp = tid >> 5;
    int wm = warp >> 2, wn = warp & 3, gr = lane >> 2, gc = lane & 3;
    int jbD = blockIdx.x;
    int ib = (NROWB - 1) - blockIdx.y;   // long blocks first
    int rowA = ib * BM, colB = jbD * BN;
    int nkt = (ib + 1) * 4;

    float acc[4][2][4];
    ACC_INIT(acc)

    const uint4* Ah4 = (const uint4*)(T_aAh + ((size_t)ib * NKT_T) * A_SLAB);
    const uint4* Al4 = (const uint4*)(T_aAl + ((size_t)ib * NKT_T) * A_SLAB);
    const uint4* Bh4 = (const uint4*)(T_hTh + ((size_t)jbD * NKT_T) * B_SLAB);
    const uint4* Bl4 = (const uint4*)(T_hTl + ((size_t)jbD * NKT_T) * B_SLAB);
    constexpr int A4W = A_SLAB / 4, B4W = B_SLAB / 4;

    uint4 ph0, ph1, pl0, pl1, qh0, ql0;
    ph0 = Ah4[tid]; ph1 = Ah4[tid + 256];
    pl0 = Al4[tid]; pl1 = Al4[tid + 256];
    qh0 = Bh4[tid]; ql0 = Bl4[tid];
    {
        uint4* S4 = (uint4*)dsm;
        S4[tid] = ph0; S4[tid + 256] = ph1;
        S4[512 + tid] = pl0; S4[512 + tid + 256] = pl1;
        S4[1024 + tid] = qh0; S4[1280 + tid] = ql0;
    }
    if (nkt > 1) {
        ph0 = Ah4[A4W + tid]; ph1 = Ah4[A4W + tid + 256];
        pl0 = Al4[A4W + tid]; pl1 = Al4[A4W + tid + 256];
        qh0 = Bh4[B4W + tid]; ql0 = Bl4[B4W + tid];
    }
    __syncthreads();

    for (int kt = 0; kt < nkt; kt++) {
        if (kt + 1 < nkt) {
            uint4* S4 = (uint4*)(dsm + ((kt + 1) & 1) * STAGE3);
            S4[tid] = ph0; S4[tid + 256] = ph1;
            S4[512 + tid] = pl0; S4[512 + tid + 256] = pl1;
            S4[1024 + tid] = qh0; S4[1280 + tid] = ql0;
        }
        if (kt + 2 < nkt) {
            size_t oa = (size_t)(kt + 2) * A4W, ob = (size_t)(kt + 2) * B4W;
            ph0 = Ah4[oa + tid]; ph1 = Ah4[oa + tid + 256];
            pl0 = Al4[oa + tid]; pl1 = Al4[oa + tid + 256];
            qh0 = Bh4[ob + tid]; ql0 = Bl4[ob + tid];
        }
        mma_body<true>(dsm + (kt & 1) * STAGE3, acc, wm, wn, lane);
        __syncthreads();
    }

    // epilogue: g fp32 (k_final) + packed bf16 A-fragments (cross)
#pragma unroll
    for (int i = 0; i < 4; i++) {
#pragma unroll
        for (int half = 0; half < 2; half++) {
            int t = rowA + (wm * 4 + i) * 16 + gr + half * 8;
            int m = t & 127;
            size_t gbase = ((size_t)(t >> 7) * NKT_FULL) * A_SLAB;
#pragma unroll
            for (int j = 0; j < 2; j++) {
                int d = colB + (wn * 2 + j) * 8 + gc * 2;
                float v0 = acc[i][j][half * 2], v1 = acc[i][j][half * 2 + 1];
                *(float2*)&g_g[(size_t)t * DD + d] = make_float2(v0, v1);
                T_gA[gbase + (size_t)(d >> 5) * A_SLAB + wordA(m, (d >> 1) & 15)] = pk(v0, v1);
            }
        }
    }
}

// ---------------- kernel 5: cross = g h^T + fused causal max (1xBF16) ------
__global__ void __launch_bounds__(256, 2) k_cross() {
    extern __shared__ unsigned dsm[];
    int tid = threadIdx.x, lane = tid & 31, warp = tid >> 5;
    int wm = warp >> 2, wn = warp & 3, gr = lane >> 2, gc = lane & 3;
    int ib, jb;
    triDecodeB(blockIdx.x, ib, jb);
    int rowA = ib * BM, rowB = jb * BN;

    float acc[4][2][4];
    ACC_INIT(acc)

    const uint4* A4 = (const uint4*)(T_gA + ((size_t)ib * NKT_FULL) * A_SLAB);
    const uint4* B4 = (const uint4*)(T_hB + ((size_t)jb * NKT_FULL) * B_SLAB);
    constexpr int A4W = A_SLAB / 4, B4W = B_SLAB / 4;

    uint4 pa0, pa1, pb0;
    pa0 = A4[tid]; pa1 = A4[tid + 256]; pb0 = B4[tid];
    {
        uint4* S4 = (uint4*)dsm;
        S4[tid] = pa0; S4[tid + 256] = pa1; S4[512 + tid] = pb0;
    }
    pa0 = A4[A4W + tid]; pa1 = A4[A4W + tid + 256]; pb0 = B4[B4W + tid];
    __syncthreads();

    for (int kt = 0; kt < NKT_FULL; kt++) {
        if (kt + 1 < NKT_FULL) {
            uint4* S4 = (uint4*)(dsm + ((kt + 1) & 1) * STAGE1);
            S4[tid] = pa0; S4[tid + 256] = pa1; S4[512 + tid] = pb0;
        }
        if (kt + 2 < NKT_FULL) {
            pa0 = A4[(size_t)(kt + 2) * A4W + tid];
            pa1 = A4[(size_t)(kt + 2) * A4W + tid + 256];
            pb0 = B4[(size_t)(kt + 2) * B4W + tid];
        }
        mma_body<false>(dsm + (kt & 1) * STAGE1, acc, wm, wn, lane);
        __syncthreads();
    }

    // epilogue: maxQ[t] = max_{s<=t}(hn2[s] - 2*cross[t,s])
    float hn[2][2];
#pragma unroll
    for (int j = 0; j < 2; j++)
#pragma unroll
        for (int e = 0; e < 2; e++)
            hn[j][e] = g_hn2[rowB + (wn * 2 + j) * 8 + gc * 2 + e];

    float* red = (float*)dsm;   // safe: all MMA reads done (post-loop sync)
#pragma unroll
    for (int i = 0; i < 4; i++) {
        int rloc = (wm * 4 + i) * 16 + gr;
        int t0 = rowA + rloc;
        float m0 = -3.0e38f, m1 = -3.0e38f;
#pragma unroll
        for (int j = 0; j < 2; j++)
#pragma unroll
            for (int e = 0; e < 2; e++) {
                int s = rowB + (wn * 2 + j) * 8 + gc * 2 + e;
                float q0 = hn[j][e] - 2.0f * acc[i][j][e];
                float q1 = hn[j][e] - 2.0f * acc[i][j][2 + e];
                if (s <= t0)     m0 = fmaxf(m0, q0);
                if (s <= t0 + 8) m1 = fmaxf(m1, q1);
            }
#pragma unroll
        for (int o = 1; o < 4; o <<= 1) {
            m0 = fmaxf(m0, __shfl_xor_sync(0xffffffffu, m0, o));
            m1 = fmaxf(m1, __shfl_xor_sync(0xffffffffu, m1, o));
        }
        if (gc == 0) {
            red[rloc * 4 + wn]       = m0;
            red[(rloc + 8) * 4 + wn] = m1;
        }
    }
    __syncthreads();
    if (tid < 128) {
        float m = fmaxf(fmaxf(red[tid * 4], red[tid * 4 + 1]),
                        fmaxf(red[tid * 4 + 2], red[tid * 4 + 3]));
        if (m > -2.0e38f) atomicMaxF(&g_maxQ[rowA + tid], m);
    }
}

// ---------------- kernel 6: final elementwise ------------------------------
__global__ void k_final(const float* __restrict__ m_t, const float* __restrict__ c_t,
                        const float* __restrict__ d_t, const float* __restrict__ mu,
                        float* __restrict__ out) {
    __shared__ float sh[32];
    int t = blockIdx.x;
    const float* hr = g_h + (size_t)t * DD;
    const float* gr = g_g + (size_t)t * DD;
    float dd = 0.f, gn2 = 0.f;
    for (int i = threadIdx.x; i < DD; i += blockDim.x) {
        float hv = hr[i], gv = gr[i];
        float df = hv - gv;
        dd += df * df;
        gn2 += gv * gv;
    }
    dd = blockReduceSum(dd, sh);
    gn2 = blockReduceSum(gn2, sh);
    if (threadIdx.x == 0) {
        float dist = sqrtf(fmaxf(dd, 1e-24f));
        float dmax = sqrtf(fmaxf(gn2 + g_maxQ[t], 1e-24f));
        if (dmax < 1e-6f) dmax = 1.0f;
        float ratio = dist / (dmax + 1e-8f);
        float stab = 1.0f - 0.3f * c_t[t] + 0.2f * d_t[t];
        float xi = 1.0f - mu[0] * m_t[t];
        float v = ratio * stab * xi;
        out[t] = fminf(fmaxf(v, 0.0f), 1.0f);
    }
}

// ---------------- launch ----------------------------------------------------
extern "C" void kernel_launch(void* const* d_in, const int* in_sizes, int n_in,
                              void* d_out, int out_size) {
    const float* x   = (const float*)d_in[0];
    const float* m_t = (const float*)d_in[1];
    const float* c_t = (const float*)d_in[2];
    const float* d_t = (const float*)d_in[3];
    const float* mu  = (const float*)d_in[4];
    float* out = (float*)d_out;

    cudaFuncSetAttribute(k_g, cudaFuncAttributeMaxDynamicSharedMemorySize, DSMEM3);

    k_normalize<<<TT, 256>>>(x);
    k_packT<<<dim3(NDB, NKT_T), 256>>>();
    k_tables<<<TT / 256, 256>>>();
    k_sim<<<NPAIRB, 256, DSMEM1>>>();
    k_softmax<<<TT, 256>>>();
    k_g<<<dim3(NDB, NROWB), 256, DSMEM3>>>();
    k_cross<<<NPAIRB, 256, DSMEM1>>>();
    k_final<<<TT, 256>>>(m_t, c_t, d_t, mu, out);
}

// round 12
// speedup vs baseline: 3.3868x; 1.1182x over previous
#include <cuda_runtime.h>
#include <cuda_bf16.h>
#include <cstdint>
#include <math.h>

#define TT 4096
#define DD 896

constexpr int NBLK = 32;                     // 128-blocks over T
constexpr int NPAIR = NBLK * (NBLK + 1) / 2; // 528 causal 128x128 pairs
constexpr int NKT_FULL = DD / 32;            // 28
constexpr int NKT_T = TT / 32;               // 128
constexpr int NDB = DD / 128;                // 7

// fragment slabs (words; 1 word = 2 bf16 = one k-pair)
constexpr int A_SLAB = 2048;                 // 128 rows x 32 k
constexpr int B_SLAB = 2048;                 // 128 cols x 32 k
constexpr int STAGE1 = A_SLAB + B_SLAB;            // 4096 words = 16 KB
constexpr int STAGE3 = 2 * (A_SLAB + B_SLAB);      // 8192 words = 32 KB
constexpr unsigned DSMEM1 = 3u * STAGE1 * 4u;      // 49152 (3-stage ring)
constexpr unsigned DSMEM3 = 3u * STAGE3 * 4u;      // 98304

// ---------------- scratch (device globals: allocation-free) ----------------
__device__ float g_h[(size_t)TT * DD];
__device__ float g_g[(size_t)TT * DD];
__device__ float g_sim[(size_t)TT * TT];
__device__ float g_hn2[TT];
__device__ float g_maxQ[TT];
__device__ float g_invden[TT];

// pre-packed bf16 fragment tables
__device__ unsigned T_hA [(size_t)NBLK * NKT_FULL * A_SLAB];  // h, A-layout hi
__device__ unsigned T_hB [(size_t)NBLK * NKT_FULL * B_SLAB];  // h, B n-major hi (128-col slabs)
__device__ unsigned T_hTh[(size_t)NDB  * NKT_T    * B_SLAB];  // h^T, B k-major hi
__device__ unsigned T_hTl[(size_t)NDB  * NKT_T    * B_SLAB];  // lo
__device__ unsigned T_aAh[(size_t)NBLK * NKT_T    * A_SLAB];  // alpha, A-layout hi
__device__ unsigned T_aAl[(size_t)NBLK * NKT_T    * A_SLAB];  // lo
__device__ unsigned T_gA [(size_t)NBLK * NKT_FULL * A_SLAB];  // g, A-layout hi

// ---------------- small helpers ----------------
__device__ __forceinline__ unsigned pk(float lo, float hi) {
    unsigned r;
    asm("cvt.rn.bf16x2.f32 %0, %1, %2;" : "=r"(r) : "f"(hi), "f"(lo));
    return r;
}
__device__ __forceinline__ void bsplit(float x, float& h, float& l) {
    h = __bfloat162float(__float2bfloat16(x));
    l = x - h;
}
__device__ __forceinline__ void mma16(float* d, const unsigned* a, const unsigned* b) {
    asm volatile(
        "mma.sync.aligned.m16n8k16.row.col.f32.bf16.bf16.f32 "
        "{%0,%1,%2,%3}, {%4,%5,%6,%7}, {%8,%9}, {%0,%1,%2,%3};\n"
        : "+f"(d[0]), "+f"(d[1]), "+f"(d[2]), "+f"(d[3])
        : "r"(a[0]), "r"(a[1]), "r"(a[2]), "r"(a[3]),
          "r"(b[0]), "r"(b[1]));
}
__device__ __forceinline__ uint32_t smem_to_u32(const void* p) {
    uint32_t a;
    asm("{ .reg .u64 t; cvta.to.shared.u64 t, %1; cvt.u32.u64 %0, t; }" : "=r"(a) : "l"(p));
    return a;
}
__device__ __forceinline__ void cpa16(uint32_t s, const void* g) {
    asm volatile("cp.async.cg.shared.global [%0], [%1], 16;" :: "r"(s), "l"(g) : "memory");
}
#define CP_COMMIT() asm volatile("cp.async.commit_group;" ::: "memory")
#define CP_WAIT1()  asm volatile("cp.async.wait_group 1;" ::: "memory")

// fragment word index within an A slab (m in 0..127, kp in 0..15)
__device__ __forceinline__ int wordA(int m, int kp) {
    int grp = (m >> 4) * 2 + (kp >> 3);
    int lane = (m & 7) * 4 + (kp & 3);
    int j = (((kp & 7) >= 4) ? 2 : 0) + (((m & 15) >= 8) ? 1 : 0);
    return grp * 128 + lane * 4 + j;
}
// fragment word index within a B slab (n in 0..127, kp in 0..15)
__device__ __forceinline__ int wordB(int n, int kp) {
    int grp = (n >> 3) * 2 + (kp >> 3);
    int lane = (n & 7) * 4 + (kp & 3);
    int j = ((kp & 7) >= 4) ? 1 : 0;
    return grp * 64 + lane * 2 + j;
}
__device__ __forceinline__ float blockReduceSum(float v, float* sh) {
    int lane = threadIdx.x & 31, w = threadIdx.x >> 5;
#pragma unroll
    for (int o = 16; o; o >>= 1) v += __shfl_xor_sync(0xffffffffu, v, o);
    __syncthreads();
    if (lane == 0) sh[w] = v;
    __syncthreads();
    if (threadIdx.x == 0) {
        float s = 0.f;
        int nw = (blockDim.x + 31) >> 5;
        for (int i = 0; i < nw; i++) s += sh[i];
        sh[0] = s;
    }
    __syncthreads();
    return sh[0];
}
__device__ __forceinline__ float blockReduceMax(float v, float* sh) {
    int lane = threadIdx.x & 31, w = threadIdx.x >> 5;
#pragma unroll
    for (int o = 16; o; o >>= 1) v = fmaxf(v, __shfl_xor_sync(0xffffffffu, v, o));
    __syncthreads();
    if (lane == 0) sh[w] = v;
    __syncthreads();
    if (threadIdx.x == 0) {
        float m = -3.0e38f;
        int nw = (blockDim.x + 31) >> 5;
        for (int i = 0; i < nw; i++) m = fmaxf(m, sh[i]);
        sh[0] = m;
    }
    __syncthreads();
    return sh[0];
}
__device__ __forceinline__ void atomicMaxF(float* addr, float val) {
    int old = __float_as_int(*addr);
    while (__int_as_float(old) < val) {
        int assumed = old;
        old = atomicCAS((int*)addr, assumed, __float_as_int(val));
        if (old == assumed) break;
    }
}
__device__ __forceinline__ void triDecode(int b, int& ib, int& jb) {
    int i = (int)floorf((sqrtf(8.0f * (float)b + 1.0f) - 1.0f) * 0.5f);
    while ((i + 1) * (i + 2) / 2 <= b) i++;
    while (i * (i + 1) / 2 > b) i--;
    ib = i;
    jb = b - i * (i + 1) / 2;
}

// ---------------- MMA over one staged 32-wide K chunk ----------------------
template <bool THREE>
__device__ __forceinline__ void mma_body(const unsigned* S, float acc[4][4][4],
                                         int wm, int wn, int lane) {
    const unsigned* Ah = S;
    const unsigned* Al = S + A_SLAB;
    const unsigned* Bh = S + (THREE ? 2 * A_SLAB : A_SLAB);
    const unsigned* Bl = Bh + B_SLAB;
#pragma unroll
    for (int ksg = 0; ksg < 2; ksg++) {
        unsigned bh[4][2], bl[4][2];
#pragma unroll
        for (int j = 0; j < 4; j++) {
            int off = ((wn * 4 + j) * 2 + ksg) * 64 + lane * 2;
            *(uint2*)bh[j] = *(const uint2*)&Bh[off];
            if (THREE) *(uint2*)bl[j] = *(const uint2*)&Bl[off];
        }
#pragma unroll
        for (int i = 0; i < 4; i++) {
            int offA = ((wm * 4 + i) * 2 + ksg) * 128 + lane * 4;
            unsigned ah[4], al[4];
            *(uint4*)ah = *(const uint4*)&Ah[offA];
            if (THREE) *(uint4*)al = *(const uint4*)&Al[offA];
#pragma unroll
            for (int j = 0; j < 4; j++) {
                if (THREE) {
                    mma16(acc[i][j], ah, bl[j]);
                    mma16(acc[i][j], al, bh[j]);
                }
                mma16(acc[i][j], ah, bh[j]);
            }
        }
    }
}

#define ACC_INIT(acc)                      \
    _Pragma("unroll")                      \
    for (int i = 0; i < 4; i++)            \
    _Pragma("unroll")                      \
    for (int j = 0; j < 4; j++)            \
    _Pragma("unroll")                      \
    for (int e = 0; e < 4; e++) acc[i][j][e] = 0.f;

// ---------------- kernel 1: normalize + pack h (A-layout, B n-major) -------
__global__ void k_normalize(const float* __restrict__ x) {
    __shared__ float sh[32];
    int t = blockIdx.x;
    const float* row = x + (size_t)t * DD;
    float ss = 0.f;
    for (int i = threadIdx.x; i < DD; i += blockDim.x) {
        float v = row[i];
        ss += v * v;
    }
    ss = blockReduceSum(ss, sh);
    float inv = 1.0f / fmaxf(sqrtf(ss), 1e-12f);
    float* hr = g_h + (size_t)t * DD;
    int mA = t & 127;
    size_t baseA = ((size_t)(t >> 7) * NKT_FULL) * A_SLAB;
    size_t baseB = ((size_t)(t >> 7) * NKT_FULL) * B_SLAB;
    for (int dp = threadIdx.x; dp < DD / 2; dp += blockDim.x) {
        int d = dp * 2;
        float v0 = row[d] * inv, v1 = row[d + 1] * inv;
        hr[d] = v0;
        hr[d + 1] = v1;
        int kt = dp >> 4, kpl = dp & 15;
        unsigned w = pk(v0, v1);
        T_hA[baseA + (size_t)kt * A_SLAB + wordA(mA, kpl)] = w;
        T_hB[baseB + (size_t)kt * B_SLAB + wordB(mA, kpl)] = w;
    }
    if (threadIdx.x == 0) {
        g_hn2[t] = ss * inv * inv;
        g_maxQ[t] = -3.0e38f;
    }
}

// ---------------- kernel 1b: pack h^T (B k-major, hi+lo) for g-GEMM --------
__global__ void k_packT() {
    __shared__ float sm[32][129];
    int jb = blockIdx.x;      // d-block (128 wide)
    int kt = blockIdx.y;      // t-chunk (32 tall)
    int tid = threadIdx.x;
#pragma unroll
    for (int it = 0; it < 16; it++) {
        int e = tid + it * 256;
        int tl = e >> 7, dl = e & 127;
        sm[tl][dl] = g_h[(size_t)(kt * 32 + tl) * DD + jb * 128 + dl];
    }
    __syncthreads();
    size_t base = ((size_t)jb * NKT_T + kt) * B_SLAB;
#pragma unroll
    for (int it = 0; it < 8; it++) {
        int w = tid + it * 256;
        int grp = w >> 6, rem = w & 63;
        int lane = rem >> 1, j = rem & 1;
        int n = (grp >> 1) * 8 + (lane >> 2);
        int kp = (grp & 1) * 8 + j * 4 + (lane & 3);
        float h0, l0, h1, l1;
        bsplit(sm[2 * kp][n], h0, l0);
        bsplit(sm[2 * kp + 1][n], h1, l1);
        T_hTh[base + w] = pk(h0, h1);
        T_hTl[base + w] = pk(l0, l1);
    }
}

__global__ void k_tables() {
    int i = blockIdx.x * 256 + threadIdx.x;
    if (i < TT)
        g_invden[i] = 1.0f / (sqrtf((float)DD) * expf(0.1f * (float)i) + 1e-8f);
}

// ---------------- kernel 2: sim = h h^T (1xBF16, cp.async 3-stage) ---------
__global__ void __launch_bounds__(256, 2) k_sim() {
    extern __shared__ unsigned dsm[];
    uint32_t sb = smem_to_u32(dsm);
    int tid = threadIdx.x, lane = tid & 31, warp = tid >> 5;
    int wm = warp >> 2, wn = warp & 3, gr = lane >> 2, gc = lane & 3;
    int ib, jb;
    triDecode(blockIdx.x, ib, jb);
    int rowA = ib * 128, rowB = jb * 128;

    float acc[4][4][4];
    ACC_INIT(acc)

    const uint4* A4 = (const uint4*)(T_hA + ((size_t)ib * NKT_FULL) * A_SLAB);
    const uint4* B4 = (const uint4*)(T_hB + ((size_t)jb * NKT_FULL) * B_SLAB);

    auto issue = [&](int kt, int buf) {
        uint32_t s = sb + (unsigned)buf * (STAGE1 * 4);
        const uint4* As = A4 + (size_t)kt * 512;
        const uint4* Bs = B4 + (size_t)kt * 512;
        cpa16(s + tid * 16, As + tid);
        cpa16(s + (tid + 256) * 16, As + tid + 256);
        cpa16(s + A_SLAB * 4 + tid * 16, Bs + tid);
        cpa16(s + A_SLAB * 4 + (tid + 256) * 16, Bs + tid + 256);
    };

    issue(0, 0); CP_COMMIT();
    issue(1, 1); CP_COMMIT();

    for (int kt = 0; kt < NKT_FULL; kt++) {
        CP_WAIT1();
        __syncthreads();
        if (kt + 2 < NKT_FULL) issue(kt + 2, (kt + 2) % 3);
        CP_COMMIT();
        mma_body<false>(dsm + (kt % 3) * STAGE1, acc, wm, wn, lane);
    }

#pragma unroll
    for (int i = 0; i < 4; i++) {
        int t = rowA + (wm * 4 + i) * 16 + gr;
#pragma unroll
        for (int j = 0; j < 4; j++) {
            int s = rowB + (wn * 4 + j) * 8 + gc * 2;
            *(float2*)&g_sim[(size_t)t * TT + s]       = make_float2(acc[i][j][0], acc[i][j][1]);
            *(float2*)&g_sim[(size_t)(t + 8) * TT + s] = make_float2(acc[i][j][2], acc[i][j][3]);
        }
    }
}

// ---------------- kernel 3: softmax -> packed alpha fragments (hi/lo) ------
__global__ void k_softmax() {
    __shared__ float sh[32];
    int t = blockIdx.x;
    float* row = g_sim + (size_t)t * TT;
    int n = t + 1;
    float lmax = -3.0e38f;
    for (int s = threadIdx.x; s < n; s += blockDim.x) {
        float l = row[s] * g_invden[t - s];
        row[s] = l;
        lmax = fmaxf(lmax, l);
    }
    lmax = blockReduceMax(lmax, sh);
    float lsum = 0.f;
    for (int s = threadIdx.x; s < n; s += blockDim.x) {
        float e = __expf(row[s] - lmax);
        row[s] = e;
        lsum += e;
    }
    lsum = blockReduceSum(lsum, sh);
    float inv = 1.0f / lsum;

    int ib = t >> 7, m = t & 127;
    size_t base = ((size_t)ib * NKT_T) * A_SLAB;
    int npairs = (ib + 1) * 64;             // covers kt < (ib+1)*4
    for (int sp = threadIdx.x; sp < npairs; sp += blockDim.x) {
        int s0 = 2 * sp, s1 = s0 + 1;
        float v0 = (s0 <= t) ? row[s0] * inv : 0.f;
        float v1 = (s1 <= t) ? row[s1] * inv : 0.f;
        float h0, l0, h1, l1;
        bsplit(v0, h0, l0);
        bsplit(v1, h1, l1);
        size_t idx = base + (size_t)(sp >> 4) * A_SLAB + wordA(m, sp & 15);
        T_aAh[idx] = pk(h0, h1);
        T_aAl[idx] = pk(l0, l1);
    }
}

// ---------------- kernel 4: g = alpha @ h (3xBF16, cp.async 3-stage) -------
__global__ void __launch_bounds__(256, 2) k_g() {
    extern __shared__ unsigned dsm[];
    uint32_t sb = smem_to_u32(dsm);
    int tid = threadIdx.x, lane = tid & 31, warp = tid >> 5;
    int wm = warp >> 2, wn = warp & 3, gr = lane >> 2, gc = lane & 3;
    int jbD = blockIdx.x;
    int ib = (NBLK - 1) - blockIdx.y;    // long blocks first
    int rowA = ib * 128, colB = jbD * 128;
    int nkt = (ib + 1) * 4;

    float acc[4][4][4];
    ACC_INIT(acc)

    const uint4* Ah4 = (const uint4*)(T_aAh + ((size_t)ib * NKT_T) * A_SLAB);
    const uint4* Al4 = (const uint4*)(T_aAl + ((size_t)ib * NKT_T) * A_SLAB);
    const uint4* Bh4 = (const uint4*)(T_hTh + ((size_t)jbD * NKT_T) * B_SLAB);
    const uint4* Bl4 = (const uint4*)(T_hTl + ((size_t)jbD * NKT_T) * B_SLAB);

    auto issue = [&](int kt, int buf) {
        uint32_t s = sb + (unsigned)buf * (STAGE3 * 4);
        size_t o = (size_t)kt * 512;
        cpa16(s + tid * 16, Ah4 + o + tid);
        cpa16(s + (tid + 256) * 16, Ah4 + o + tid + 256);
        cpa16(s + 8192 + tid * 16, Al4 + o + tid);
        cpa16(s + 8192 + (tid + 256) * 16, Al4 + o + tid + 256);
        cpa16(s + 16384 + tid * 16, Bh4 + o + tid);
        cpa16(s + 16384 + (tid + 256) * 16, Bh4 + o + tid + 256);
        cpa16(s + 24576 + tid * 16, Bl4 + o + tid);
        cpa16(s + 24576 + (tid + 256) * 16, Bl4 + o + tid + 256);
    };

    issue(0, 0); CP_COMMIT();
    issue(1, 1); CP_COMMIT();

    for (int kt = 0; kt < nkt; kt++) {
        CP_WAIT1();
        __syncthreads();
        if (kt + 2 < nkt) issue(kt + 2, (kt + 2) % 3);
        CP_COMMIT();
        mma_body<true>(dsm + (kt % 3) * STAGE3, acc, wm, wn, lane);
    }

    // epilogue: g fp32 (k_final) + packed bf16 A-fragments (cross)
#pragma unroll
    for (int i = 0; i < 4; i++) {
#pragma unroll
        for (int half = 0; half < 2; half++) {
            int t = rowA + (wm * 4 + i) * 16 + gr + half * 8;
            int m = t & 127;
            size_t gbase = ((size_t)(t >> 7) * NKT_FULL) * A_SLAB;
#pragma unroll
            for (int j = 0; j < 4; j++) {
                int d = colB + (wn * 4 + j) * 8 + gc * 2;
                float v0 = acc[i][j][half * 2], v1 = acc[i][j][half * 2 + 1];
                *(float2*)&g_g[(size_t)t * DD + d] = make_float2(v0, v1);
                T_gA[gbase + (size_t)(d >> 5) * A_SLAB + wordA(m, (d >> 1) & 15)] = pk(v0, v1);
            }
        }
    }
}

// ---------------- kernel 5: cross = g h^T + fused causal max (1xBF16) ------
__global__ void __launch_bounds__(256, 2) k_cross() {
    extern __shared__ unsigned dsm[];
    uint32_t sb = smem_to_u32(dsm);
    int tid = threadIdx.x, lane = tid & 31, warp = tid >> 5;
    int wm = warp >> 2, wn = warp & 3, gr = lane >> 2, gc = lane & 3;
    int ib, jb;
    triDecode(blockIdx.x, ib, jb);
    int rowA = ib * 128, rowB = jb * 128;

    float acc[4][4][4];
    ACC_INIT(acc)

    const uint4* A4 = (const uint4*)(T_gA + ((size_t)ib * NKT_FULL) * A_SLAB);
    const uint4* B4 = (const uint4*)(T_hB + ((size_t)jb * NKT_FULL) * B_SLAB);

    auto issue = [&](int kt, int buf) {
        uint32_t s = sb + (unsigned)buf * (STAGE1 * 4);
        const uint4* As = A4 + (size_t)kt * 512;
        const uint4* Bs = B4 + (size_t)kt * 512;
        cpa16(s + tid * 16, As + tid);
        cpa16(s + (tid + 256) * 16, As + tid + 256);
        cpa16(s + A_SLAB * 4 + tid * 16, Bs + tid);
        cpa16(s + A_SLAB * 4 + (tid + 256) * 16, Bs + tid + 256);
    };

    issue(0, 0); CP_COMMIT();
    issue(1, 1); CP_COMMIT();

    for (int kt = 0; kt < NKT_FULL; kt++) {
        CP_WAIT1();
        __syncthreads();
        if (kt + 2 < NKT_FULL) issue(kt + 2, (kt + 2) % 3);
        CP_COMMIT();
        mma_body<false>(dsm + (kt % 3) * STAGE1, acc, wm, wn, lane);
    }

    // epilogue: maxQ[t] = max_{s<=t}(hn2[s] - 2*cross[t,s])
    float hn[4][2];
#pragma unroll
    for (int j = 0; j < 4; j++)
#pragma unroll
        for (int e = 0; e < 2; e++)
            hn[j][e] = g_hn2[rowB + (wn * 4 + j) * 8 + gc * 2 + e];

    __syncthreads();                 // all MMA smem reads done; reuse dsm
    float* red = (float*)dsm;
#pragma unroll
    for (int i = 0; i < 4; i++) {
        int rloc = (wm * 4 + i) * 16 + gr;
        int t0 = rowA + rloc;
        float m0 = -3.0e38f, m1 = -3.0e38f;
#pragma unroll
        for (int j = 0; j < 4; j++)
#pragma unroll
            for (int e = 0; e < 2; e++) {
                int s = rowB + (wn * 4 + j) * 8 + gc * 2 + e;
                float q0 = hn[j][e] - 2.0f * acc[i][j][e];
                float q1 = hn[j][e] - 2.0f * acc[i][j][2 + e];
                if (s <= t0)     m0 = fmaxf(m0, q0);
                if (s <= t0 + 8) m1 = fmaxf(m1, q1);
            }
#pragma unroll
        for (int o = 1; o < 4; o <<= 1) {
            m0 = fmaxf(m0, __shfl_xor_sync(0xffffffffu, m0, o));
            m1 = fmaxf(m1, __shfl_xor_sync(0xffffffffu, m1, o));
        }
        if (gc == 0) {
            red[rloc * 4 + wn]       = m0;
            red[(rloc + 8) * 4 + wn] = m1;
        }
    }
    __syncthreads();
    if (tid < 128) {
        float m = fmaxf(fmaxf(red[tid * 4], red[tid * 4 + 1]),
                        fmaxf(red[tid * 4 + 2], red[tid * 4 + 3]));
        if (m > -2.0e38f) atomicMaxF(&g_maxQ[rowA + tid], m);
    }
}

// ---------------- kernel 6: final elementwise ------------------------------
__global__ void k_final(const float* __restrict__ m_t, const float* __restrict__ c_t,
                        const float* __restrict__ d_t, const float* __restrict__ mu,
                        float* __restrict__ out) {
    __shared__ float sh[32];
    int t = blockIdx.x;
    const float* hr = g_h + (size_t)t * DD;
    const float* gr = g_g + (size_t)t * DD;
    float dd = 0.f, gn2 = 0.f;
    for (int i = threadIdx.x; i < DD; i += blockDim.x) {
        float hv = hr[i], gv = gr[i];
        float df = hv - gv;
        dd += df * df;
        gn2 += gv * gv;
    }
    dd = blockReduceSum(dd, sh);
    gn2 = blockReduceSum(gn2, sh);
    if (threadIdx.x == 0) {
        float dist = sqrtf(fmaxf(dd, 1e-24f));
        float dmax = sqrtf(fmaxf(gn2 + g_maxQ[t], 1e-24f));
        if (dmax < 1e-6f) dmax = 1.0f;
        float ratio = dist / (dmax + 1e-8f);
        float stab = 1.0f - 0.3f * c_t[t] + 0.2f * d_t[t];
        float xi = 1.0f - mu[0] * m_t[t];
        float v = ratio * stab * xi;
        out[t] = fminf(fmaxf(v, 0.0f), 1.0f);
    }
}

// ---------------- launch ----------------------------------------------------
extern "C" void kernel_launch(void* const* d_in, const int* in_sizes, int n_in,
                              void* d_out, int out_size) {
    const float* x   = (const float*)d_in[0];
    const float* m_t = (const float*)d_in[1];
    const float* c_t = (const float*)d_in[2];
    const float* d_t = (const float*)d_in[3];
    const float* mu  = (const float*)d_in[4];
    float* out = (float*)d_out;

    cudaFuncSetAttribute(k_sim,   cudaFuncAttributeMaxDynamicSharedMemorySize, DSMEM1);
    cudaFuncSetAttribute(k_g,     cudaFuncAttributeMaxDynamicSharedMemorySize, DSMEM3);
    cudaFuncSetAttribute(k_cross, cudaFuncAttributeMaxDynamicSharedMemorySize, DSMEM1);

    k_normalize<<<TT, 256>>>(x);
    k_packT<<<dim3(NDB, NKT_T), 256>>>();
    k_tables<<<TT / 256, 256>>>();
    k_sim<<<NPAIR, 256, DSMEM1>>>();
    k_softmax<<<TT, 256>>>();
    k_g<<<dim3(NDB, NBLK), 256, DSMEM3>>>();
    k_cross<<<NPAIR, 256, DSMEM1>>>();
    k_final<<<TT, 256>>>(m_t, c_t, d_t, mu, out);
}

// round 13
// speedup vs baseline: 3.4161x; 1.0086x over previous
#include <cuda_runtime.h>
#include <cuda_bf16.h>
#include <cstdint>
#include <math.h>

#define TT 4096
#define DD 896

constexpr int NBLK = 32;                     // 128-blocks over T
constexpr int NPAIR = NBLK * (NBLK + 1) / 2; // 528 causal 128x128 pairs
constexpr int NKT_FULL = DD / 32;            // 28
constexpr int NKT2 = NKT_FULL / 2;           // 14 double-ktiles (BK=64)
constexpr int NKT_T = TT / 32;               // 128
constexpr int NDB = DD / 128;                // 7

// fragment slabs (words; 1 word = 2 bf16 = one k-pair)
constexpr int A_SLAB = 2048;                 // 128 rows x 32 k
constexpr int B_SLAB = 2048;                 // 128 cols x 32 k
constexpr int STAGE1 = 2 * (A_SLAB + B_SLAB);      // BK=64 1x stage: 8192 w = 32 KB
constexpr int STAGE3 = 2 * (A_SLAB + B_SLAB);      // BK=32 3x stage: 8192 w = 32 KB
constexpr unsigned DSMEM1 = 3u * STAGE1 * 4u;      // 98304 (3-stage ring)
constexpr unsigned DSMEM3 = 3u * STAGE3 * 4u;      // 98304
constexpr unsigned DSMEM_SM = 16384;               // softmax row buffer

// ---------------- scratch (device globals: allocation-free) ----------------
__device__ float g_h[(size_t)TT * DD];
__device__ float g_g[(size_t)TT * DD];
__device__ float g_sim[(size_t)TT * TT];
__device__ float g_hn2[TT];
__device__ float g_maxQ[TT];
__device__ float g_invden[TT];

// pre-packed bf16 fragment tables
__device__ unsigned T_hA [(size_t)NBLK * NKT_FULL * A_SLAB];  // h, A-layout hi
__device__ unsigned T_hB [(size_t)NBLK * NKT_FULL * B_SLAB];  // h, B n-major hi
__device__ unsigned T_hTh[(size_t)NDB  * NKT_T    * B_SLAB];  // h^T, B k-major hi
__device__ unsigned T_hTl[(size_t)NDB  * NKT_T    * B_SLAB];  // lo
__device__ unsigned T_aAh[(size_t)NBLK * NKT_T    * A_SLAB];  // alpha, A-layout hi
__device__ unsigned T_aAl[(size_t)NBLK * NKT_T    * A_SLAB];  // lo
__device__ unsigned T_gA [(size_t)NBLK * NKT_FULL * A_SLAB];  // g, A-layout hi

// ---------------- small helpers ----------------
__device__ __forceinline__ unsigned pk(float lo, float hi) {
    unsigned r;
    asm("cvt.rn.bf16x2.f32 %0, %1, %2;" : "=r"(r) : "f"(hi), "f"(lo));
    return r;
}
__device__ __forceinline__ void bsplit(float x, float& h, float& l) {
    h = __bfloat162float(__float2bfloat16(x));
    l = x - h;
}
__device__ __forceinline__ void mma16(float* d, const unsigned* a, const unsigned* b) {
    asm volatile(
        "mma.sync.aligned.m16n8k16.row.col.f32.bf16.bf16.f32 "
        "{%0,%1,%2,%3}, {%4,%5,%6,%7}, {%8,%9}, {%0,%1,%2,%3};\n"
        : "+f"(d[0]), "+f"(d[1]), "+f"(d[2]), "+f"(d[3])
        : "r"(a[0]), "r"(a[1]), "r"(a[2]), "r"(a[3]),
          "r"(b[0]), "r"(b[1]));
}
__device__ __forceinline__ uint32_t smem_to_u32(const void* p) {
    uint32_t a;
    asm("{ .reg .u64 t; cvta.to.shared.u64 t, %1; cvt.u32.u64 %0, t; }" : "=r"(a) : "l"(p));
    return a;
}
__device__ __forceinline__ void cpa16(uint32_t s, const void* g) {
    asm volatile("cp.async.cg.shared.global [%0], [%1], 16;" :: "r"(s), "l"(g) : "memory");
}
#define CP_COMMIT() asm volatile("cp.async.commit_group;" ::: "memory")
#define CP_WAIT1()  asm volatile("cp.async.wait_group 1;" ::: "memory")

// fragment word index within an A slab (m in 0..127, kp in 0..15)
__device__ __forceinline__ int wordA(int m, int kp) {
    int grp = (m >> 4) * 2 + (kp >> 3);
    int lane = (m & 7) * 4 + (kp & 3);
    int j = (((kp & 7) >= 4) ? 2 : 0) + (((m & 15) >= 8) ? 1 : 0);
    return grp * 128 + lane * 4 + j;
}
// fragment word index within a B slab (n in 0..127, kp in 0..15)
__device__ __forceinline__ int wordB(int n, int kp) {
    int grp = (n >> 3) * 2 + (kp >> 3);
    int lane = (n & 7) * 4 + (kp & 3);
    int j = ((kp & 7) >= 4) ? 1 : 0;
    return grp * 64 + lane * 2 + j;
}
__device__ __forceinline__ float blockReduceSum(float v, float* sh) {
    int lane = threadIdx.x & 31, w = threadIdx.x >> 5;
#pragma unroll
    for (int o = 16; o; o >>= 1) v += __shfl_xor_sync(0xffffffffu, v, o);
    __syncthreads();
    if (lane == 0) sh[w] = v;
    __syncthreads();
    if (threadIdx.x == 0) {
        float s = 0.f;
        int nw = (blockDim.x + 31) >> 5;
        for (int i = 0; i < nw; i++) s += sh[i];
        sh[0] = s;
    }
    __syncthreads();
    return sh[0];
}
__device__ __forceinline__ float blockReduceMax(float v, float* sh) {
    int lane = threadIdx.x & 31, w = threadIdx.x >> 5;
#pragma unroll
    for (int o = 16; o; o >>= 1) v = fmaxf(v, __shfl_xor_sync(0xffffffffu, v, o));
    __syncthreads();
    if (lane == 0) sh[w] = v;
    __syncthreads();
    if (threadIdx.x == 0) {
        float m = -3.0e38f;
        int nw = (blockDim.x + 31) >> 5;
        for (int i = 0; i < nw; i++) m = fmaxf(m, sh[i]);
        sh[0] = m;
    }
    __syncthreads();
    return sh[0];
}
__device__ __forceinline__ void atomicMaxF(float* addr, float val) {
    int old = __float_as_int(*addr);
    while (__int_as_float(old) < val) {
        int assumed = old;
        old = atomicCAS((int*)addr, assumed, __float_as_int(val));
        if (old == assumed) break;
    }
}
__device__ __forceinline__ void triDecode(int b, int& ib, int& jb) {
    int i = (int)floorf((sqrtf(8.0f * (float)b + 1.0f) - 1.0f) * 0.5f);
    while ((i + 1) * (i + 2) / 2 <= b) i++;
    while (i * (i + 1) / 2 > b) i--;
    ib = i;
    jb = b - i * (i + 1) / 2;
}

// ---------------- MMA over one 32-wide K slab pair (A ptr, B ptr) ----------
// THREE: Al = A + A_SLAB, Bl = B + B_SLAB (hi/lo compensated)
template <bool THREE>
__device__ __forceinline__ void mma_part(const unsigned* A, const unsigned* B,
                                         float acc[4][4][4], int wm, int wn, int lane) {
    const unsigned* Al = A + A_SLAB;
    const unsigned* Bl = B + B_SLAB;
#pragma unroll
    for (int ksg = 0; ksg < 2; ksg++) {
        unsigned bh[4][2], bl[4][2];
#pragma unroll
        for (int j = 0; j < 4; j++) {
            int off = ((wn * 4 + j) * 2 + ksg) * 64 + lane * 2;
            *(uint2*)bh[j] = *(const uint2*)&B[off];
            if (THREE) *(uint2*)bl[j] = *(const uint2*)&Bl[off];
        }
#pragma unroll
        for (int i = 0; i < 4; i++) {
            int offA = ((wm * 4 + i) * 2 + ksg) * 128 + lane * 4;
            unsigned ah[4], al[4];
            *(uint4*)ah = *(const uint4*)&A[offA];
            if (THREE) *(uint4*)al = *(const uint4*)&Al[offA];
#pragma unroll
            for (int j = 0; j < 4; j++) {
                if (THREE) {
                    mma16(acc[i][j], ah, bl[j]);
                    mma16(acc[i][j], al, bh[j]);
                }
                mma16(acc[i][j], ah, bh[j]);
            }
        }
    }
}

#define ACC_INIT(acc)                      \
    _Pragma("unroll")                      \
    for (int i = 0; i < 4; i++)            \
    _Pragma("unroll")                      \
    for (int j = 0; j < 4; j++)            \
    _Pragma("unroll")                      \
    for (int e = 0; e < 4; e++) acc[i][j][e] = 0.f;

// ---------------- kernel 1: normalize + pack h (A-layout, B n-major) -------
__global__ void k_normalize(const float* __restrict__ x) {
    __shared__ float sh[32];
    int t = blockIdx.x;
    const float* row = x + (size_t)t * DD;
    float ss = 0.f;
    for (int i = threadIdx.x; i < DD; i += blockDim.x) {
        float v = row[i];
        ss += v * v;
    }
    ss = blockReduceSum(ss, sh);
    float inv = 1.0f / fmaxf(sqrtf(ss), 1e-12f);
    float* hr = g_h + (size_t)t * DD;
    int mA = t & 127;
    size_t baseA = ((size_t)(t >> 7) * NKT_FULL) * A_SLAB;
    size_t baseB = ((size_t)(t >> 7) * NKT_FULL) * B_SLAB;
    for (int dp = threadIdx.x; dp < DD / 2; dp += blockDim.x) {
        int d = dp * 2;
        float v0 = row[d] * inv, v1 = row[d + 1] * inv;
        hr[d] = v0;
        hr[d + 1] = v1;
        int kt = dp >> 4, kpl = dp & 15;
        unsigned w = pk(v0, v1);
        T_hA[baseA + (size_t)kt * A_SLAB + wordA(mA, kpl)] = w;
        T_hB[baseB + (size_t)kt * B_SLAB + wordB(mA, kpl)] = w;
    }
    if (threadIdx.x == 0) {
        g_hn2[t] = ss * inv * inv;
        g_maxQ[t] = -3.0e38f;
    }
}

// ---------------- kernel 1b: pack h^T (B k-major, hi+lo) for g-GEMM --------
__global__ void k_packT() {
    __shared__ float sm[32][129];
    int jb = blockIdx.x;      // d-block (128 wide)
    int kt = blockIdx.y;      // t-chunk (32 tall)
    int tid = threadIdx.x;
#pragma unroll
    for (int it = 0; it < 16; it++) {
        int e = tid + it * 256;
        int tl = e >> 7, dl = e & 127;
        sm[tl][dl] = g_h[(size_t)(kt * 32 + tl) * DD + jb * 128 + dl];
    }
    __syncthreads();
    size_t base = ((size_t)jb * NKT_T + kt) * B_SLAB;
#pragma unroll
    for (int it = 0; it < 8; it++) {
        int w = tid + it * 256;
        int grp = w >> 6, rem = w & 63;
        int lane = rem >> 1, j = rem & 1;
        int n = (grp >> 1) * 8 + (lane >> 2);
        int kp = (grp & 1) * 8 + j * 4 + (lane & 3);
        float h0, l0, h1, l1;
        bsplit(sm[2 * kp][n], h0, l0);
        bsplit(sm[2 * kp + 1][n], h1, l1);
        T_hTh[base + w] = pk(h0, h1);
        T_hTl[base + w] = pk(l0, l1);
    }
}

__global__ void k_tables() {
    int i = blockIdx.x * 256 + threadIdx.x;
    if (i < TT)
        g_invden[i] = 1.0f / (sqrtf((float)DD) * expf(0.1f * (float)i) + 1e-8f);
}

// ---------------- kernel 2: sim = h h^T (1xBF16, BK=64, cp.async ring) -----
__global__ void __launch_bounds__(256, 2) k_sim() {
    extern __shared__ unsigned dsm[];
    uint32_t sb = smem_to_u32(dsm);
    int tid = threadIdx.x, lane = tid & 31, warp = tid >> 5;
    int wm = warp >> 2, wn = warp & 3, gr = lane >> 2, gc = lane & 3;
    int ib, jb;
    triDecode(blockIdx.x, ib, jb);
    int rowA = ib * 128, rowB = jb * 128;

    float acc[4][4][4];
    ACC_INIT(acc)

    const uint4* A4 = (const uint4*)(T_hA + ((size_t)ib * NKT_FULL) * A_SLAB);
    const uint4* B4 = (const uint4*)(T_hB + ((size_t)jb * NKT_FULL) * B_SLAB);

    // stage layout (words): [A0 A1 | B0 B1], each slab 2048
    auto issue = [&](int k2, int buf) {
        uint32_t s = sb + (unsigned)buf * (STAGE1 * 4);
        const uint4* As = A4 + (size_t)k2 * 1024;
        const uint4* Bs = B4 + (size_t)k2 * 1024;
#pragma unroll
        for (int it = 0; it < 4; it++) {
            cpa16(s + (tid + it * 256) * 16, As + tid + it * 256);
            cpa16(s + 16384 + (tid + it * 256) * 16, Bs + tid + it * 256);
        }
    };

    issue(0, 0); CP_COMMIT();
    issue(1, 1); CP_COMMIT();

    for (int k2 = 0; k2 < NKT2; k2++) {
        CP_WAIT1();
        __syncthreads();
        if (k2 + 2 < NKT2) issue(k2 + 2, (k2 + 2) % 3);
        CP_COMMIT();
        const unsigned* S = dsm + (k2 % 3) * STAGE1;
        mma_part<false>(S, S + 4096, acc, wm, wn, lane);
        mma_part<false>(S + 2048, S + 6144, acc, wm, wn, lane);
    }

#pragma unroll
    for (int i = 0; i < 4; i++) {
        int t = rowA + (wm * 4 + i) * 16 + gr;
#pragma unroll
        for (int j = 0; j < 4; j++) {
            int s = rowB + (wn * 4 + j) * 8 + gc * 2;
            *(float2*)&g_sim[(size_t)t * TT + s]       = make_float2(acc[i][j][0], acc[i][j][1]);
            *(float2*)&g_sim[(size_t)(t + 8) * TT + s] = make_float2(acc[i][j][2], acc[i][j][3]);
        }
    }
}

// ---------------- kernel 3: softmax (smem row) -> packed alpha fragments ---
__global__ void k_softmax() {
    extern __shared__ float srow[];       // up to 4096 floats
    __shared__ float sh[32];
    int t = blockIdx.x;
    const float* row = g_sim + (size_t)t * TT;
    int n = t + 1;
    float lmax = -3.0e38f;
    for (int s = threadIdx.x; s < n; s += blockDim.x) {
        float l = row[s] * g_invden[t - s];
        srow[s] = l;
        lmax = fmaxf(lmax, l);
    }
    lmax = blockReduceMax(lmax, sh);
    float lsum = 0.f;
    for (int s = threadIdx.x; s < n; s += blockDim.x) {
        float e = __expf(srow[s] - lmax);
        srow[s] = e;
        lsum += e;
    }
    lsum = blockReduceSum(lsum, sh);
    float inv = 1.0f / lsum;

    int ib = t >> 7, m = t & 127;
    size_t base = ((size_t)ib * NKT_T) * A_SLAB;
    int npairs = (ib + 1) * 64;           // covers kt < (ib+1)*4
    for (int sp = threadIdx.x; sp < npairs; sp += blockDim.x) {
        int s0 = 2 * sp, s1 = s0 + 1;
        float v0 = (s0 <= t) ? srow[s0] * inv : 0.f;
        float v1 = (s1 <= t) ? srow[s1] * inv : 0.f;
        float h0, l0, h1, l1;
        bsplit(v0, h0, l0);
        bsplit(v1, h1, l1);
        size_t idx = base + (size_t)(sp >> 4) * A_SLAB + wordA(m, sp & 15);
        T_aAh[idx] = pk(h0, h1);
        T_aAl[idx] = pk(l0, l1);
    }
}

// ---------------- kernel 4: g = alpha @ h (3xBF16, BK=32, cp.async ring) ---
__global__ void __launch_bounds__(256, 2) k_g() {
    extern __shared__ unsigned dsm[];
    uint32_t sb = smem_to_u32(dsm);
    int tid = threadIdx.x, lane = tid & 31, warp = tid >> 5;
    int wm = warp >> 2, wn = warp & 3, gr = lane >> 2, gc = lane & 3;
    int jbD = blockIdx.x;
    int ib = (NBLK - 1) - blockIdx.y;     // long blocks first
    int rowA = ib * 128, colB = jbD * 128;
    int nkt = (ib + 1) * 4;

    float acc[4][4][4];
    ACC_INIT(acc)

    const uint4* Ah4 = (const uint4*)(T_aAh + ((size_t)ib * NKT_T) * A_SLAB);
    const uint4* Al4 = (const uint4*)(T_aAl + ((size_t)ib * NKT_T) * A_SLAB);
    const uint4* Bh4 = (const uint4*)(T_hTh + ((size_t)jbD * NKT_T) * B_SLAB);
    const uint4* Bl4 = (const uint4*)(T_hTl + ((size_t)jbD * NKT_T) * B_SLAB);

    // stage layout: [Ah Al | Bh Bl], each slab 2048 words
    auto issue = [&](int kt, int buf) {
        uint32_t s = sb + (unsigned)buf * (STAGE3 * 4);
        size_t o = (size_t)kt * 512;
#pragma unroll
        for (int it = 0; it < 2; it++) {
            cpa16(s + (tid + it * 256) * 16, Ah4 + o + tid + it * 256);
            cpa16(s + 8192 + (tid + it * 256) * 16, Al4 + o + tid + it * 256);
            cpa16(s + 16384 + (tid + it * 256) * 16, Bh4 + o + tid + it * 256);
            cpa16(s + 24576 + (tid + it * 256) * 16, Bl4 + o + tid + it * 256);
        }
    };

    issue(0, 0); CP_COMMIT();
    issue(1, 1); CP_COMMIT();

    for (int kt = 0; kt < nkt; kt++) {
        CP_WAIT1();
        __syncthreads();
        if (kt + 2 < nkt) issue(kt + 2, (kt + 2) % 3);
        CP_COMMIT();
        const unsigned* S = dsm + (kt % 3) * STAGE3;
        mma_part<true>(S, S + 4096, acc, wm, wn, lane);
    }

    // epilogue: g fp32 (k_final) + packed bf16 A-fragments (cross)
#pragma unroll
    for (int i = 0; i < 4; i++) {
#pragma unroll
        for (int half = 0; half < 2; half++) {
            int t = rowA + (wm * 4 + i) * 16 + gr + half * 8;
            int m = t & 127;
            size_t gbase = ((size_t)(t >> 7) * NKT_FULL) * A_SLAB;
#pragma unroll
            for (int j = 0; j < 4; j++) {
                int d = colB + (wn * 4 + j) * 8 + gc * 2;
                float v0 = acc[i][j][half * 2], v1 = acc[i][j][half * 2 + 1];
                *(float2*)&g_g[(size_t)t * DD + d] = make_float2(v0, v1);
                T_gA[gbase + (size_t)(d >> 5) * A_SLAB + wordA(m, (d >> 1) & 15)] = pk(v0, v1);
            }
        }
    }
}

// ---------------- kernel 5: cross = g h^T + fused causal max (1xBF16) ------
__global__ void __launch_bounds__(256, 2) k_cross() {
    extern __shared__ unsigned dsm[];
    uint32_t sb = smem_to_u32(dsm);
    int tid = threadIdx.x, lane = tid & 31, warp = tid >> 5;
    int wm = warp >> 2, wn = warp & 3, gr = lane >> 2, gc = lane & 3;
    int ib, jb;
    triDecode(blockIdx.x, ib, jb);
    int rowA = ib * 128, rowB = jb * 128;

    float acc[4][4][4];
    ACC_INIT(acc)

    const uint4* A4 = (const uint4*)(T_gA + ((size_t)ib * NKT_FULL) * A_SLAB);
    const uint4* B4 = (const uint4*)(T_hB + ((size_t)jb * NKT_FULL) * B_SLAB);

    auto issue = [&](int k2, int buf) {
        uint32_t s = sb + (unsigned)buf * (STAGE1 * 4);
        const uint4* As = A4 + (size_t)k2 * 1024;
        const uint4* Bs = B4 + (size_t)k2 * 1024;
#pragma unroll
        for (int it = 0; it < 4; it++) {
            cpa16(s + (tid + it * 256) * 16, As + tid + it * 256);
            cpa16(s + 16384 + (tid + it * 256) * 16, Bs + tid + it * 256);
        }
    };

    issue(0, 0); CP_COMMIT();
    issue(1, 1); CP_COMMIT();

    for (int k2 = 0; k2 < NKT2; k2++) {
        CP_WAIT1();
        __syncthreads();
        if (k2 + 2 < NKT2) issue(k2 + 2, (k2 + 2) % 3);
        CP_COMMIT();
        const unsigned* S = dsm + (k2 % 3) * STAGE1;
        mma_part<false>(S, S + 4096, acc, wm, wn, lane);
        mma_part<false>(S + 2048, S + 6144, acc, wm, wn, lane);
    }

    // epilogue: maxQ[t] = max_{s<=t}(hn2[s] - 2*cross[t,s])
    float hn[4][2];
#pragma unroll
    for (int j = 0; j < 4; j++)
#pragma unroll
        for (int e = 0; e < 2; e++)
            hn[j][e] = g_hn2[rowB + (wn * 4 + j) * 8 + gc * 2 + e];

    __syncthreads();                 // all MMA smem reads done; reuse dsm
    float* red = (float*)dsm;
#pragma unroll
    for (int i = 0; i < 4; i++) {
        int rloc = (wm * 4 + i) * 16 + gr;
        int t0 = rowA + rloc;
        float m0 = -3.0e38f, m1 = -3.0e38f;
#pragma unroll
        for (int j = 0; j < 4; j++)
#pragma unroll
            for (int e = 0; e < 2; e++) {
                int s = rowB + (wn * 4 + j) * 8 + gc * 2 + e;
                float q0 = hn[j][e] - 2.0f * acc[i][j][e];
                float q1 = hn[j][e] - 2.0f * acc[i][j][2 + e];
                if (s <= t0)     m0 = fmaxf(m0, q0);
                if (s <= t0 + 8) m1 = fmaxf(m1, q1);
            }
#pragma unroll
        for (int o = 1; o < 4; o <<= 1) {
            m0 = fmaxf(m0, __shfl_xor_sync(0xffffffffu, m0, o));
            m1 = fmaxf(m1, __shfl_xor_sync(0xffffffffu, m1, o));
        }
        if (gc == 0) {
            red[rloc * 4 + wn]       = m0;
            red[(rloc + 8) * 4 + wn] = m1;
        }
    }
    __syncthreads();
    if (tid < 128) {
        float m = fmaxf(fmaxf(red[tid * 4], red[tid * 4 + 1]),
                        fmaxf(red[tid * 4 + 2], red[tid * 4 + 3]));
        if (m > -2.0e38f) atomicMaxF(&g_maxQ[rowA + tid], m);
    }
}

// ---------------- kernel 6: final elementwise ------------------------------
__global__ void k_final(const float* __restrict__ m_t, const float* __restrict__ c_t,
                        const float* __restrict__ d_t, const float* __restrict__ mu,
                        float* __restrict__ out) {
    __shared__ float sh[32];
    int t = blockIdx.x;
    const float* hr = g_h + (size_t)t * DD;
    const float* gr = g_g + (size_t)t * DD;
    float dd = 0.f, gn2 = 0.f;
    for (int i = threadIdx.x; i < DD; i += blockDim.x) {
        float hv = hr[i], gv = gr[i];
        float df = hv - gv;
        dd += df * df;
        gn2 += gv * gv;
    }
    dd = blockReduceSum(dd, sh);
    gn2 = blockReduceSum(gn2, sh);
    if (threadIdx.x == 0) {
        float dist = sqrtf(fmaxf(dd, 1e-24f));
        float dmax = sqrtf(fmaxf(gn2 + g_maxQ[t], 1e-24f));
        if (dmax < 1e-6f) dmax = 1.0f;
        float ratio = dist / (dmax + 1e-8f);
        float stab = 1.0f - 0.3f * c_t[t] + 0.2f * d_t[t];
        float xi = 1.0f - mu[0] * m_t[t];
        float v = ratio * stab * xi;
        out[t] = fminf(fmaxf(v, 0.0f), 1.0f);
    }
}

// ---------------- launch ----------------------------------------------------
extern "C" void kernel_launch(void* const* d_in, const int* in_sizes, int n_in,
                              void* d_out, int out_size) {
    const float* x   = (const float*)d_in[0];
    const float* m_t = (const float*)d_in[1];
    const float* c_t = (const float*)d_in[2];
    const float* d_t = (const float*)d_in[3];
    const float* mu  = (const float*)d_in[4];
    float* out = (float*)d_out;

    cudaFuncSetAttribute(k_sim,     cudaFuncAttributeMaxDynamicSharedMemorySize, DSMEM1);
    cudaFuncSetAttribute(k_g,       cudaFuncAttributeMaxDynamicSharedMemorySize, DSMEM3);
    cudaFuncSetAttribute(k_cross,   cudaFuncAttributeMaxDynamicSharedMemorySize, DSMEM1);
    cudaFuncSetAttribute(k_softmax, cudaFuncAttributeMaxDynamicSharedMemorySize, DSMEM_SM);

    k_normalize<<<TT, 256>>>(x);
    k_packT<<<dim3(NDB, NKT_T), 256>>>();
    k_tables<<<TT / 256, 256>>>();
    k_sim<<<NPAIR, 256, DSMEM1>>>();
    k_softmax<<<TT, 256, DSMEM_SM>>>();
    k_g<<<dim3(NDB, NBLK), 256, DSMEM3>>>();
    k_cross<<<NPAIR, 256, DSMEM1>>>();
    k_final<<<TT, 256>>>(m_t, c_t, d_t, mu, out);
}

// round 15
// speedup vs baseline: 4.0172x; 1.1760x over previous
#include <cuda_runtime.h>
#include <cuda_bf16.h>
#include <cstdint>
#include <math.h>

#define TT 4096
#define DD 896

constexpr int NBLK = 32;                     // 128-blocks over T
constexpr int NPAIR = NBLK * (NBLK + 1) / 2; // 528 causal 128x128 pairs
constexpr int NKT_FULL = DD / 32;            // 28
constexpr int NKT2 = NKT_FULL / 2;           // 14 double-ktiles (BK=64)
constexpr int NKT_T = TT / 32;               // 128
constexpr int NDB = DD / 128;                // 7

// fragment slabs (words; 1 word = 2 bf16 = one k-pair)
constexpr int A_SLAB = 2048;                 // 128 rows x 32 k
constexpr int B_SLAB = 2048;                 // 128 cols x 32 k
constexpr int STAGE1 = 2 * (A_SLAB + B_SLAB);   // BK=64 1x stage: 8192 w = 32 KB
constexpr int STAGE3 = 2 * (A_SLAB + B_SLAB);   // g stage (Ah,Al,Bh,Bl): 32 KB
constexpr unsigned DSMEM1 = 3u * STAGE1 * 4u;   // 98304
constexpr unsigned DSMEM3 = 3u * STAGE3 * 4u;   // 98304
constexpr unsigned DSMEM_SM = 16384;            // softmax row buffer

// ---------------- scratch (device globals: allocation-free) ----------------
__device__ float g_h[(size_t)TT * DD];
__device__ float g_g[(size_t)TT * DD];
__device__ float g_part0[(size_t)TT * DD];
__device__ float g_part1[(size_t)TT * DD];
__device__ float g_sim[(size_t)TT * TT];
__device__ float g_hn2[TT];
__device__ float g_maxQ[TT];
__device__ float g_invden[TT];

// pre-packed bf16 fragment tables
__device__ unsigned T_hA [(size_t)NBLK * NKT_FULL * A_SLAB];  // h, A-layout hi
__device__ unsigned T_hB [(size_t)NBLK * NKT_FULL * B_SLAB];  // h, B n-major hi
__device__ unsigned T_hTh[(size_t)NDB  * NKT_T    * B_SLAB];  // h^T, B k-major hi
__device__ unsigned T_hTl[(size_t)NDB  * NKT_T    * B_SLAB];  // lo
__device__ unsigned T_aAh[(size_t)NBLK * NKT_T    * A_SLAB];  // alpha, A-layout hi
__device__ unsigned T_aAl[(size_t)NBLK * NKT_T    * A_SLAB];  // lo
__device__ unsigned T_gA [(size_t)NBLK * NKT_FULL * A_SLAB];  // g, A-layout hi

// ---------------- small helpers ----------------
__device__ __forceinline__ unsigned pk(float lo, float hi) {
    unsigned r;
    asm("cvt.rn.bf16x2.f32 %0, %1, %2;" : "=r"(r) : "f"(hi), "f"(lo));
    return r;
}
__device__ __forceinline__ void bsplit(float x, float& h, float& l) {
    h = __bfloat162float(__float2bfloat16(x));
    l = x - h;
}
__device__ __forceinline__ void mma16(float* d, const unsigned* a, const unsigned* b) {
    asm volatile(
        "mma.sync.aligned.m16n8k16.row.col.f32.bf16.bf16.f32 "
        "{%0,%1,%2,%3}, {%4,%5,%6,%7}, {%8,%9}, {%0,%1,%2,%3};\n"
        : "+f"(d[0]), "+f"(d[1]), "+f"(d[2]), "+f"(d[3])
        : "r"(a[0]), "r"(a[1]), "r"(a[2]), "r"(a[3]),
          "r"(b[0]), "r"(b[1]));
}
__device__ __forceinline__ uint32_t smem_to_u32(const void* p) {
    uint32_t a;
    asm("{ .reg .u64 t; cvta.to.shared.u64 t, %1; cvt.u32.u64 %0, t; }" : "=r"(a) : "l"(p));
    return a;
}
__device__ __forceinline__ void cpa16(uint32_t s, const void* g) {
    asm volatile("cp.async.cg.shared.global [%0], [%1], 16;" :: "r"(s), "l"(g) : "memory");
}
#define CP_COMMIT() asm volatile("cp.async.commit_group;" ::: "memory")
#define CP_WAIT1()  asm volatile("cp.async.wait_group 1;" ::: "memory")

// fragment word index within an A slab (m in 0..127, kp in 0..15)
__device__ __forceinline__ int wordA(int m, int kp) {
    int grp = (m >> 4) * 2 + (kp >> 3);
    int lane = (m & 7) * 4 + (kp & 3);
    int j = (((kp & 7) >= 4) ? 2 : 0) + (((m & 15) >= 8) ? 1 : 0);
    return grp * 128 + lane * 4 + j;
}
// fragment word index within a B slab (n in 0..127, kp in 0..15)
__device__ __forceinline__ int wordB(int n, int kp) {
    int grp = (n >> 3) * 2 + (kp >> 3);
    int lane = (n & 7) * 4 + (kp & 3);
    int j = ((kp & 7) >= 4) ? 1 : 0;
    return grp * 64 + lane * 2 + j;
}
__device__ __forceinline__ float blockReduceSum(float v, float* sh) {
    int lane = threadIdx.x & 31, w = threadIdx.x >> 5;
#pragma unroll
    for (int o = 16; o; o >>= 1) v += __shfl_xor_sync(0xffffffffu, v, o);
    __syncthreads();
    if (lane == 0) sh[w] = v;
    __syncthreads();
    if (threadIdx.x == 0) {
        float s = 0.f;
        int nw = (blockDim.x + 31) >> 5;
        for (int i = 0; i < nw; i++) s += sh[i];
        sh[0] = s;
    }
    __syncthreads();
    return sh[0];
}
__device__ __forceinline__ float blockReduceMax(float v, float* sh) {
    int lane = threadIdx.x & 31, w = threadIdx.x >> 5;
#pragma unroll
    for (int o = 16; o; o >>= 1) v = fmaxf(v, __shfl_xor_sync(0xffffffffu, v, o));
    __syncthreads();
    if (lane == 0) sh[w] = v;
    __syncthreads();
    if (threadIdx.x == 0) {
        float m = -3.0e38f;
        int nw = (blockDim.x + 31) >> 5;
        for (int i = 0; i < nw; i++) m = fmaxf(m, sh[i]);
        sh[0] = m;
    }
    __syncthreads();
    return sh[0];
}
__device__ __forceinline__ void atomicMaxF(float* addr, float val) {
    int old = __float_as_int(*addr);
    while (__int_as_float(old) < val) {
        int assumed = old;
        old = atomicCAS((int*)addr, assumed, __float_as_int(val));
        if (old == assumed) break;
    }
}
__device__ __forceinline__ void triDecode(int b, int& ib, int& jb) {
    int i = (int)floorf((sqrtf(8.0f * (float)b + 1.0f) - 1.0f) * 0.5f);
    while ((i + 1) * (i + 2) / 2 <= b) i++;
    while (i * (i + 1) / 2 > b) i--;
    ib = i;
    jb = b - i * (i + 1) / 2;
}

// ---------------- MMA bodies ----------------
// 1x: plain hi*hi
__device__ __forceinline__ void mma_part1(const unsigned* A, const unsigned* B,
                                          float acc[4][4][4], int wm, int wn, int lane) {
#pragma unroll
    for (int ksg = 0; ksg < 2; ksg++) {
        unsigned bh[4][2];
#pragma unroll
        for (int j = 0; j < 4; j++) {
            int off = ((wn * 4 + j) * 2 + ksg) * 64 + lane * 2;
            *(uint2*)bh[j] = *(const uint2*)&B[off];
        }
#pragma unroll
        for (int i = 0; i < 4; i++) {
            int offA = ((wm * 4 + i) * 2 + ksg) * 128 + lane * 4;
            unsigned ah[4];
            *(uint4*)ah = *(const uint4*)&A[offA];
#pragma unroll
            for (int j = 0; j < 4; j++) mma16(acc[i][j], ah, bh[j]);
        }
    }
}
// 3x: ah*bl + al*bh + ah*bh (full compensation; Al = A+A_SLAB, Bl = B+B_SLAB)
__device__ __forceinline__ void mma_part3(const unsigned* A, const unsigned* B,
                                          float acc[4][4][4], int wm, int wn, int lane) {
    const unsigned* Al = A + A_SLAB;
    const unsigned* Bl = B + B_SLAB;
#pragma unroll
    for (int ksg = 0; ksg < 2; ksg++) {
        unsigned bh[4][2], bl[4][2];
#pragma unroll
        for (int j = 0; j < 4; j++) {
            int off = ((wn * 4 + j) * 2 + ksg) * 64 + lane * 2;
            *(uint2*)bh[j] = *(const uint2*)&B[off];
            *(uint2*)bl[j] = *(const uint2*)&Bl[off];
        }
#pragma unroll
        for (int i = 0; i < 4; i++) {
            int offA = ((wm * 4 + i) * 2 + ksg) * 128 + lane * 4;
            unsigned ah[4], al[4];
            *(uint4*)ah = *(const uint4*)&A[offA];
            *(uint4*)al = *(const uint4*)&Al[offA];
#pragma unroll
            for (int j = 0; j < 4; j++) {
                mma16(acc[i][j], ah, bl[j]);
                mma16(acc[i][j], al, bh[j]);
                mma16(acc[i][j], ah, bh[j]);
            }
        }
    }
}

#define ACC_INIT(acc)                      \
    _Pragma("unroll")                      \
    for (int i = 0; i < 4; i++)            \
    _Pragma("unroll")                      \
    for (int j = 0; j < 4; j++)            \
    _Pragma("unroll")                      \
    for (int e = 0; e < 4; e++) acc[i][j][e] = 0.f;

// ---------------- kernel 1: normalize + pack h (A-layout, B n-major) -------
__global__ void k_normalize(const float* __restrict__ x) {
    __shared__ float sh[32];
    int t = blockIdx.x;
    const float* row = x + (size_t)t * DD;
    float ss = 0.f;
    for (int i = threadIdx.x; i < DD; i += blockDim.x) {
        float v = row[i];
        ss += v * v;
    }
    ss = blockReduceSum(ss, sh);
    float inv = 1.0f / fmaxf(sqrtf(ss), 1e-12f);
    float* hr = g_h + (size_t)t * DD;
    int mA = t & 127;
    size_t baseA = ((size_t)(t >> 7) * NKT_FULL) * A_SLAB;
    size_t baseB = ((size_t)(t >> 7) * NKT_FULL) * B_SLAB;
    for (int dp = threadIdx.x; dp < DD / 2; dp += blockDim.x) {
        int d = dp * 2;
        float v0 = row[d] * inv, v1 = row[d + 1] * inv;
        hr[d] = v0;
        hr[d + 1] = v1;
        int kt = dp >> 4, kpl = dp & 15;
        unsigned w = pk(v0, v1);
        T_hA[baseA + (size_t)kt * A_SLAB + wordA(mA, kpl)] = w;
        T_hB[baseB + (size_t)kt * B_SLAB + wordB(mA, kpl)] = w;
    }
    if (threadIdx.x == 0) {
        g_hn2[t] = ss * inv * inv;
        g_maxQ[t] = -3.0e38f;
    }
}

// ---------------- kernel 1b: pack h^T (B k-major, hi+lo) for g-GEMM --------
__global__ void k_packT() {
    __shared__ float sm[32][129];
    int jb = blockIdx.x;      // d-block (128 wide)
    int kt = blockIdx.y;      // t-chunk (32 tall)
    int tid = threadIdx.x;
#pragma unroll
    for (int it = 0; it < 16; it++) {
        int e = tid + it * 256;
        int tl = e >> 7, dl = e & 127;
        sm[tl][dl] = g_h[(size_t)(kt * 32 + tl) * DD + jb * 128 + dl];
    }
    __syncthreads();
    size_t base = ((size_t)jb * NKT_T + kt) * B_SLAB;
#pragma unroll
    for (int it = 0; it < 8; it++) {
        int w = tid + it * 256;
        int grp = w >> 6, rem = w & 63;
        int lane = rem >> 1, j = rem & 1;
        int n = (grp >> 1) * 8 + (lane >> 2);
        int kp = (grp & 1) * 8 + j * 4 + (lane & 3);
        float h0, l0, h1, l1;
        bsplit(sm[2 * kp][n], h0, l0);
        bsplit(sm[2 * kp + 1][n], h1, l1);
        T_hTh[base + w] = pk(h0, h1);
        T_hTl[base + w] = pk(l0, l1);
    }
}

__global__ void k_tables() {
    int i = blockIdx.x * 256 + threadIdx.x;
    if (i < TT)
        g_invden[i] = 1.0f / (sqrtf((float)DD) * expf(0.1f * (float)i) + 1e-8f);
}

// ---------------- kernel 2: sim = h h^T (1xBF16, BK=64, cp.async ring) -----
__global__ void __launch_bounds__(256, 2) k_sim() {
    extern __shared__ unsigned dsm[];
    uint32_t sb = smem_to_u32(dsm);
    int tid = threadIdx.x, lane = tid & 31, warp = tid >> 5;
    int wm = warp >> 2, wn = warp & 3, gr = lane >> 2, gc = lane & 3;
    int ib, jb;
    triDecode(blockIdx.x, ib, jb);
    int rowA = ib * 128, rowB = jb * 128;

    float acc[4][4][4];
    ACC_INIT(acc)

    const uint4* A4 = (const uint4*)(T_hA + ((size_t)ib * NKT_FULL) * A_SLAB);
    const uint4* B4 = (const uint4*)(T_hB + ((size_t)jb * NKT_FULL) * B_SLAB);

    auto issue = [&](int k2, int buf) {
        uint32_t s = sb + (unsigned)buf * (STAGE1 * 4);
        const uint4* As = A4 + (size_t)k2 * 1024;
        const uint4* Bs = B4 + (size_t)k2 * 1024;
#pragma unroll
        for (int it = 0; it < 4; it++) {
            cpa16(s + (tid + it * 256) * 16, As + tid + it * 256);
            cpa16(s + 16384 + (tid + it * 256) * 16, Bs + tid + it * 256);
        }
    };

    issue(0, 0); CP_COMMIT();
    issue(1, 1); CP_COMMIT();

    for (int k2 = 0; k2 < NKT2; k2++) {
        CP_WAIT1();
        __syncthreads();
        if (k2 + 2 < NKT2) issue(k2 + 2, (k2 + 2) % 3);
        CP_COMMIT();
        const unsigned* S = dsm + (k2 % 3) * STAGE1;
        mma_part1(S, S + 4096, acc, wm, wn, lane);
        mma_part1(S + 2048, S + 6144, acc, wm, wn, lane);
    }

#pragma unroll
    for (int i = 0; i < 4; i++) {
        int t = rowA + (wm * 4 + i) * 16 + gr;
#pragma unroll
        for (int j = 0; j < 4; j++) {
            int s = rowB + (wn * 4 + j) * 8 + gc * 2;
            *(float2*)&g_sim[(size_t)t * TT + s]       = make_float2(acc[i][j][0], acc[i][j][1]);
            *(float2*)&g_sim[(size_t)(t + 8) * TT + s] = make_float2(acc[i][j][2], acc[i][j][3]);
        }
    }
}

// ---------------- kernel 3: softmax (smem row) -> packed alpha fragments ---
__global__ void k_softmax() {
    extern __shared__ float srow[];
    __shared__ float sh[32];
    int t = blockIdx.x;
    const float* row = g_sim + (size_t)t * TT;
    int n = t + 1;
    float lmax = -3.0e38f;
    for (int s = threadIdx.x; s < n; s += blockDim.x) {
        float l = row[s] * g_invden[t - s];
        srow[s] = l;
        lmax = fmaxf(lmax, l);
    }
    lmax = blockReduceMax(lmax, sh);
    float lsum = 0.f;
    for (int s = threadIdx.x; s < n; s += blockDim.x) {
        float e = __expf(srow[s] - lmax);
        srow[s] = e;
        lsum += e;
    }
    lsum = blockReduceSum(lsum, sh);
    float inv = 1.0f / lsum;

    int ib = t >> 7, m = t & 127;
    size_t base = ((size_t)ib * NKT_T) * A_SLAB;
    int npairs = (ib + 1) * 64;
    for (int sp = threadIdx.x; sp < npairs; sp += blockDim.x) {
        int s0 = 2 * sp, s1 = s0 + 1;
        float v0 = (s0 <= t) ? srow[s0] * inv : 0.f;
        float v1 = (s1 <= t) ? srow[s1] * inv : 0.f;
        float h0, l0, h1, l1;
        bsplit(v0, h0, l0);
        bsplit(v1, h1, l1);
        size_t idx = base + (size_t)(sp >> 4) * A_SLAB + wordA(m, sp & 15);
        T_aAh[idx] = pk(h0, h1);
        T_aAl[idx] = pk(l0, l1);
    }
}

// ---------------- kernel 4: g = alpha @ h (3xBF16, split-K=2) --------------
__global__ void __launch_bounds__(256, 2) k_g() {
    extern __shared__ unsigned dsm[];
    uint32_t sb = smem_to_u32(dsm);
    int tid = threadIdx.x, lane = tid & 31, warp = tid >> 5;
    int wm = warp >> 2, wn = warp & 3, gr = lane >> 2, gc = lane & 3;
    int jbD = blockIdx.x;
    int ib = (NBLK - 1) - blockIdx.y;     // long blocks first
    int z = blockIdx.z;                   // k-split half
    int rowA = ib * 128, colB = jbD * 128;
    int nkt = (ib + 1) * 4;
    int beg = z ? nkt / 2 : 0;
    int end = z ? nkt : nkt / 2;

    float acc[4][4][4];
    ACC_INIT(acc)

    const uint4* Ah4 = (const uint4*)(T_aAh + ((size_t)ib * NKT_T) * A_SLAB);
    const uint4* Al4 = (const uint4*)(T_aAl + ((size_t)ib * NKT_T) * A_SLAB);
    const uint4* Bh4 = (const uint4*)(T_hTh + ((size_t)jbD * NKT_T) * B_SLAB);
    const uint4* Bl4 = (const uint4*)(T_hTl + ((size_t)jbD * NKT_T) * B_SLAB);

    // stage layout: [Ah(2048) Al(2048) Bh(2048) Bl(2048)] words
    auto issue = [&](int kt, int buf) {
        uint32_t s = sb + (unsigned)buf * (STAGE3 * 4);
        size_t o = (size_t)kt * 512;
#pragma unroll
        for (int it = 0; it < 2; it++) {
            cpa16(s + (tid + it * 256) * 16, Ah4 + o + tid + it * 256);
            cpa16(s + 8192 + (tid + it * 256) * 16, Al4 + o + tid + it * 256);
            cpa16(s + 16384 + (tid + it * 256) * 16, Bh4 + o + tid + it * 256);
            cpa16(s + 24576 + (tid + it * 256) * 16, Bl4 + o + tid + it * 256);
        }
    };

    issue(beg, 0); CP_COMMIT();
    issue(beg + 1, 1); CP_COMMIT();       // end-beg >= 2 always

    int cnt = end - beg;
    for (int i = 0; i < cnt; i++) {
        CP_WAIT1();
        __syncthreads();
        if (i + 2 < cnt) issue(beg + i + 2, (i + 2) % 3);
        CP_COMMIT();
        const unsigned* S = dsm + (i % 3) * STAGE3;
        mma_part3(S, S + 4096, acc, wm, wn, lane);
    }

    float* dst = z ? g_part1 : g_part0;
#pragma unroll
    for (int i = 0; i < 4; i++) {
#pragma unroll
        for (int half = 0; half < 2; half++) {
            int t = rowA + (wm * 4 + i) * 16 + gr + half * 8;
#pragma unroll
            for (int j = 0; j < 4; j++) {
                int d = colB + (wn * 4 + j) * 8 + gc * 2;
                *(float2*)&dst[(size_t)t * DD + d] =
                    make_float2(acc[i][j][half * 2], acc[i][j][half * 2 + 1]);
            }
        }
    }
}

// ---------------- kernel 4b: g = part0 + part1; write fp32 + packed frags --
__global__ void k_gred() {
    int t = blockIdx.x;
    int m = t & 127;
    size_t roff = (size_t)t * DD;
    size_t gbase = ((size_t)(t >> 7) * NKT_FULL) * A_SLAB;
    for (int dp = threadIdx.x; dp < DD / 2; dp += blockDim.x) {
        int d = dp * 2;
        float2 a = *(const float2*)&g_part0[roff + d];
        float2 b = *(const float2*)&g_part1[roff + d];
        float v0 = a.x + b.x, v1 = a.y + b.y;
        *(float2*)&g_g[roff + d] = make_float2(v0, v1);
        T_gA[gbase + (size_t)(dp >> 4) * A_SLAB + wordA(m, dp & 15)] = pk(v0, v1);
    }
}

// ---------------- kernel 5: cross = g h^T + fused causal max (1xBF16) ------
__global__ void __launch_bounds__(256, 2) k_cross() {
    extern __shared__ unsigned dsm[];
    uint32_t sb = smem_to_u32(dsm);
    int tid = threadIdx.x, lane = tid & 31, warp = tid >> 5;
    int wm = warp >> 2, wn = warp & 3, gr = lane >> 2, gc = lane & 3;
    int ib, jb;
    triDecode(blockIdx.x, ib, jb);
    int rowA = ib * 128, rowB = jb * 128;

    float acc[4][4][4];
    ACC_INIT(acc)

    const uint4* A4 = (const uint4*)(T_gA + ((size_t)ib * NKT_FULL) * A_SLAB);
    const uint4* B4 = (const uint4*)(T_hB + ((size_t)jb * NKT_FULL) * B_SLAB);

    auto issue = [&](int k2, int buf) {
        uint32_t s = sb + (unsigned)buf * (STAGE1 * 4);
        const uint4* As = A4 + (size_t)k2 * 1024;
        const uint4* Bs = B4 + (size_t)k2 * 1024;
#pragma unroll
        for (int it = 0; it < 4; it++) {
            cpa16(s + (tid + it * 256) * 16, As + tid + it * 256);
            cpa16(s + 16384 + (tid + it * 256) * 16, Bs + tid + it * 256);
        }
    };

    issue(0, 0); CP_COMMIT();
    issue(1, 1); CP_COMMIT();

    for (int k2 = 0; k2 < NKT2; k2++) {
        CP_WAIT1();
        __syncthreads();
        if (k2 + 2 < NKT2) issue(k2 + 2, (k2 + 2) % 3);
        CP_COMMIT();
        const unsigned* S = dsm + (k2 % 3) * STAGE1;
        mma_part1(S, S + 4096, acc, wm, wn, lane);
        mma_part1(S + 2048, S + 6144, acc, wm, wn, lane);
    }

    // epilogue: maxQ[t] = max_{s<=t}(hn2[s] - 2*cross[t,s])
    float hn[4][2];
#pragma unroll
    for (int j = 0; j < 4; j++)
#pragma unroll
        for (int e = 0; e < 2; e++)
            hn[j][e] = g_hn2[rowB + (wn * 4 + j) * 8 + gc * 2 + e];

    __syncthreads();
    float* red = (float*)dsm;
#pragma unroll
    for (int i = 0; i < 4; i++) {
        int rloc = (wm * 4 + i) * 16 + gr;
        int t0 = rowA + rloc;
        float m0 = -3.0e38f, m1 = -3.0e38f;
#pragma unroll
        for (int j = 0; j < 4; j++)
#pragma unroll
            for (int e = 0; e < 2; e++) {
                int s = rowB + (wn * 4 + j) * 8 + gc * 2 + e;
                float q0 = hn[j][e] - 2.0f * acc[i][j][e];
                float q1 = hn[j][e] - 2.0f * acc[i][j][2 + e];
                if (s <= t0)     m0 = fmaxf(m0, q0);
                if (s <= t0 + 8) m1 = fmaxf(m1, q1);
            }
#pragma unroll
        for (int o = 1; o < 4; o <<= 1) {
            m0 = fmaxf(m0, __shfl_xor_sync(0xffffffffu, m0, o));
            m1 = fmaxf(m1, __shfl_xor_sync(0xffffffffu, m1, o));
        }
        if (gc == 0) {
            red[rloc * 4 + wn]       = m0;
            red[(rloc + 8) * 4 + wn] = m1;
        }
    }
    __syncthreads();
    if (tid < 128) {
        float m = fmaxf(fmaxf(red[tid * 4], red[tid * 4 + 1]),
                        fmaxf(red[tid * 4 + 2], red[tid * 4 + 3]));
        if (m > -2.0e38f) atomicMaxF(&g_maxQ[rowA + tid], m);
    }
}

// ---------------- kernel 6: final elementwise ------------------------------
__global__ void k_final(const float* __restrict__ m_t, const float* __restrict__ c_t,
                        const float* __restrict__ d_t, const float* __restrict__ mu,
                        float* __restrict__ out) {
    __shared__ float sh[32];
    int t = blockIdx.x;
    const float* hr = g_h + (size_t)t * DD;
    const float* gr = g_g + (size_t)t * DD;
    float dd = 0.f, gn2 = 0.f;
    for (int i = threadIdx.x; i < DD; i += blockDim.x) {
        float hv = hr[i], gv = gr[i];
        float df = hv - gv;
        dd += df * df;
        gn2 += gv * gv;
    }
    dd = blockReduceSum(dd, sh);
    gn2 = blockReduceSum(gn2, sh);
    if (threadIdx.x == 0) {
        float dist = sqrtf(fmaxf(dd, 1e-24f));
        float dmax = sqrtf(fmaxf(gn2 + g_maxQ[t], 1e-24f));
        if (dmax < 1e-6f) dmax = 1.0f;
        float ratio = dist / (dmax + 1e-8f);
        float stab = 1.0f - 0.3f * c_t[t] + 0.2f * d_t[t];
        float xi = 1.0f - mu[0] * m_t[t];
        float v = ratio * stab * xi;
        out[t] = fminf(fmaxf(v, 0.0f), 1.0f);
    }
}

// ---------------- launch ----------------------------------------------------
extern "C" void kernel_launch(void* const* d_in, const int* in_sizes, int n_in,
                              void* d_out, int out_size) {
    const float* x   = (const float*)d_in[0];
    const float* m_t = (const float*)d_in[1];
    const float* c_t = (const float*)d_in[2];
    const float* d_t = (const float*)d_in[3];
    const float* mu  = (const float*)d_in[4];
    float* out = (float*)d_out;

    cudaFuncSetAttribute(k_sim,     cudaFuncAttributeMaxDynamicSharedMemorySize, DSMEM1);
    cudaFuncSetAttribute(k_g,       cudaFuncAttributeMaxDynamicSharedMemorySize, DSMEM3);
    cudaFuncSetAttribute(k_cross,   cudaFuncAttributeMaxDynamicSharedMemorySize, DSMEM1);
    cudaFuncSetAttribute(k_softmax, cudaFuncAttributeMaxDynamicSharedMemorySize, DSMEM_SM);

    k_normalize<<<TT, 256>>>(x);
    k_packT<<<dim3(NDB, NKT_T), 256>>>();
    k_tables<<<TT / 256, 256>>>();
    k_sim<<<NPAIR, 256, DSMEM1>>>();
    k_softmax<<<TT, 256, DSMEM_SM>>>();
    k_g<<<dim3(NDB, NBLK, 2), 256, DSMEM3>>>();
    k_gred<<<TT, 256>>>();
    k_cross<<<NPAIR, 256, DSMEM1>>>();
    k_final<<<TT, 256>>>(m_t, c_t, d_t, mu, out);
}